// round 13
// baseline (speedup 1.0000x reference)
#include <cuda_runtime.h>
#include <cuda_fp16.h>
#include <math.h>

#define NH   12
#define D    64
#define SEQ  1024
#define BAT  4
#define HID  768
#define BS   4096      // BAT*SEQ
#define POS  512       // 2*span
#define SPAN 256

// -------- scratch (static device memory; no allocations) --------
// q,k,posk,posq are stored with the K(=D) dimension PERMUTED within 8-col groups:
// logical r (r=j&7) stored at position (r&3)*2 + (r>>2). Dot products over K are
// permutation-invariant, so all MMA results are unchanged; fragment loads become
// 64-bit pairs (qt, qt+4 adjacent).
__device__ float  g_q[BS * HID];                   // tf32-rounded, K-permuted
__device__ float  g_k[BS * HID];                   // tf32-rounded, K-permuted
__device__ float  g_v[BS * HID];                   // tf32-rounded, [b][h][d][s]
__device__ float  g_ctx[BS * HID];                 // tf32-rounded
__device__ float  g_pre[BS * HID];
__device__ float  g_posk[POS * HID];               // tf32-rounded, K-permuted
__device__ float  g_posq[POS * HID];               // tf32-rounded, K-permuted
__device__ __half g_c2p[(size_t)NH * BS * POS];    // [h][b*S+s][512] fp16
__device__ __half g_p2cT[(size_t)NH * POS * BS];   // [h][bucket][b*S+t] fp16
__device__ int    g_c2pidx[2048];

// -------- relative-position bucket table (matches numpy exactly) --------
// p2c's gather index equals c2p's (log-bucket map is odd-symmetric); one table.
__global__ void relb_kernel() {
    int i = blockIdx.x * blockDim.x + threadIdx.x;
    if (i >= 2047) return;
    int rel = i - 1023;
    const int mid = 128;
    int sgn = (rel > 0) - (rel < 0);
    float abs_pos = (rel < mid && rel > -mid) ? (float)(mid - 1) : (float)abs(rel);
    float num32 = logf(abs_pos / 128.0f);
    double log_pos = ceil((double)num32 / log(511.0 / 128.0) * 127.0) + 128.0;
    long long bucket = (abs_pos <= 128.0f) ? (long long)rel
                                           : (long long)(log_pos * (double)sgn);
    int bi = (int)bucket;
    int c = bi + SPAN;  c = c < 0 ? 0 : (c > 2 * SPAN - 1 ? 2 * SPAN - 1 : c);
    g_c2pidx[i] = c;
}

// -------- tf32 helpers --------
__device__ __forceinline__ float f2tf(float x) {
    unsigned u;
    asm("cvt.rna.tf32.f32 %0, %1;" : "=r"(u) : "f"(x));
    return __uint_as_float(u);
}
__device__ __forceinline__ unsigned f2tfu(float x) {
    unsigned u;
    asm("cvt.rna.tf32.f32 %0, %1;" : "=r"(u) : "f"(x));
    return u;
}

__device__ __forceinline__ void mma_tf32(float* c, const unsigned* a, const unsigned* b) {
    asm volatile(
        "mma.sync.aligned.m16n8k8.row.col.f32.tf32.tf32.f32 "
        "{%0,%1,%2,%3},{%4,%5,%6,%7},{%8,%9},{%0,%1,%2,%3};"
        : "+f"(c[0]), "+f"(c[1]), "+f"(c[2]), "+f"(c[3])
        : "r"(a[0]), "r"(a[1]), "r"(a[2]), "r"(a[3]), "r"(b[0]), "r"(b[1]));
}

__device__ __forceinline__ void cp_async16(unsigned dst, const void* src) {
    asm volatile("cp.async.cg.shared.global [%0], [%1], 16;\n" :: "r"(dst), "l"(src));
}

// permuted column position (within 8-groups)
__device__ __forceinline__ long long permc(long long j) {
    int r = (int)(j & 7);
    return (j & ~7LL) | ((r & 3) * 2 + (r >> 2));
}

// ======== generic NT GEMM with 4-stage cp.async ring ========
// C[TM x TN] tile (TM=128; TN 64 or 128). 256 threads. BK=16.
// CVTA/CVTB: tf32 cvt at fragment load. RND: round fp32 outputs to tf32.
// PERM: operands K-permuted -> paired 64-bit fragment loads.
// PERMOUT: store outputs with K-permutation (scalar stores).
// EPI: 0 plain, 1 +bias, 2 +bias+resid, 3 +bias, scatter vT
template<int EPI, int TM, int TN, bool CVTA, bool CVTB, bool RND, bool PERM, bool PERMOUT, typename OutT>
__device__ __forceinline__ void gemm_body(
    const float* __restrict__ A, int lda,
    const float* __restrict__ B, int ldb,
    const float* __restrict__ bias,
    const float* __restrict__ resid, int ldr,
    OutT* __restrict__ C, long long ldc, int K,
    int row0, int col0)
{
    constexpr int MI = 2;
    constexpr int NI = (TN == 64) ? 4 : 8;
    constexpr int ROWS = TM + TN;
    constexpr int CP = ROWS / 64;
    extern __shared__ float S[];          // [4][ROWS][20]
    int tid = threadIdx.x;
    int wid = tid >> 5, lane = tid & 31;
    int quad = lane >> 2, qt = lane & 3;
    int wm, wn;
    if (TN == 64) { wm = (wid >> 1) * 32; wn = (wid & 1) * 32; }
    else          { wm = (wid & 3) * 32;  wn = (wid >> 2) * 64; }

    const float* gsrc[CP];
    unsigned soff[CP];
    unsigned sbase = (unsigned)__cvta_generic_to_shared(S);
#pragma unroll
    for (int j = 0; j < CP; j++) {
        int lin = tid + j * 256;
        int row = lin >> 2, c4 = (lin & 3) * 4;
        soff[j] = row * 20 + c4;
        gsrc[j] = (row < TM) ? A + (long long)(row0 + row) * lda + c4
                             : B + (long long)(col0 + row - TM) * ldb + c4;
    }
    auto issue = [&](int cc) {
        int slot = cc & 3;
        long long k0 = (long long)cc * 16;
#pragma unroll
        for (int j = 0; j < CP; j++)
            cp_async16(sbase + (slot * ROWS * 20 + soff[j]) * 4, gsrc[j] + k0);
        asm volatile("cp.async.commit_group;\n");
    };

    float acc[MI][NI][4];
#pragma unroll
    for (int i = 0; i < MI; i++)
#pragma unroll
        for (int j = 0; j < NI; j++)
#pragma unroll
            for (int l = 0; l < 4; l++) acc[i][j][l] = 0.0f;

    auto ldA = [&](const float* p) -> unsigned {
        return CVTA ? f2tfu(*p) : __float_as_uint(*p);
    };
    auto ldB = [&](const float* p) -> unsigned {
        return CVTB ? f2tfu(*p) : __float_as_uint(*p);
    };

    auto comp = [&](int slot) {
        const float* Sb = S + slot * ROWS * 20;
#pragma unroll
        for (int kk = 0; kk < 16; kk += 8) {
            unsigned af[MI][4], bfr[NI][2];
            if (PERM) {
#pragma unroll
                for (int mi = 0; mi < MI; mi++) {
                    int r = wm + mi * 16 + quad;
                    float2 a0 = *reinterpret_cast<const float2*>(&Sb[r * 20 + kk + 2 * qt]);
                    float2 a1 = *reinterpret_cast<const float2*>(&Sb[(r + 8) * 20 + kk + 2 * qt]);
                    af[mi][0] = __float_as_uint(a0.x);
                    af[mi][1] = __float_as_uint(a1.x);
                    af[mi][2] = __float_as_uint(a0.y);
                    af[mi][3] = __float_as_uint(a1.y);
                }
#pragma unroll
                for (int ni = 0; ni < NI; ni++) {
                    int n = TM + wn + ni * 8 + quad;
                    float2 b0 = *reinterpret_cast<const float2*>(&Sb[n * 20 + kk + 2 * qt]);
                    bfr[ni][0] = __float_as_uint(b0.x);
                    bfr[ni][1] = __float_as_uint(b0.y);
                }
            } else {
#pragma unroll
                for (int mi = 0; mi < MI; mi++) {
                    int r = wm + mi * 16 + quad;
                    af[mi][0] = ldA(&Sb[r * 20 + kk + qt]);
                    af[mi][1] = ldA(&Sb[(r + 8) * 20 + kk + qt]);
                    af[mi][2] = ldA(&Sb[r * 20 + kk + qt + 4]);
                    af[mi][3] = ldA(&Sb[(r + 8) * 20 + kk + qt + 4]);
                }
#pragma unroll
                for (int ni = 0; ni < NI; ni++) {
                    int n = TM + wn + ni * 8 + quad;
                    bfr[ni][0] = ldB(&Sb[n * 20 + kk + qt]);
                    bfr[ni][1] = ldB(&Sb[n * 20 + kk + qt + 4]);
                }
            }
#pragma unroll
            for (int mi = 0; mi < MI; mi++)
#pragma unroll
                for (int ni = 0; ni < NI; ni++)
                    mma_tf32(acc[mi][ni], af[mi], bfr[ni]);
        }
    };

    int nst = K >> 4;
    issue(0); issue(1); issue(2);
    for (int c = 0; c < nst; c++) {
        asm volatile("cp.async.wait_group %0;\n" :: "n"(2));
        __syncthreads();
        if (c + 3 < nst) issue(c + 3);
        else asm volatile("cp.async.commit_group;\n");
        comp(c & 3);
    }

    // epilogue
#pragma unroll
    for (int mi = 0; mi < MI; mi++) {
#pragma unroll
        for (int half = 0; half < 2; half++) {
            long long row = row0 + wm + mi * 16 + quad + half * 8;
#pragma unroll
            for (int ni = 0; ni < NI; ni++) {
                long long col = col0 + wn + ni * 8 + qt * 2;
                float v0 = acc[mi][ni][half * 2 + 0];
                float v1 = acc[mi][ni][half * 2 + 1];
                if (EPI >= 1) { v0 += bias[col]; v1 += bias[col + 1]; }
                if (EPI == 2) {
                    v0 += resid[row * ldr + col];
                    v1 += resid[row * ldr + col + 1];
                }
                if (RND) { v0 = f2tf(v0); v1 = f2tf(v1); }
                if (EPI == 3) {
                    int bb = (int)(row >> 10), ss = (int)(row & 1023);
                    int hh = (int)(col >> 6), dd = (int)(col & 63);
                    ((float*)C)[((((long long)bb * NH + hh) * D + dd) << 10) + ss] = v0;
                    hh = (int)((col + 1) >> 6); dd = (int)((col + 1) & 63);
                    ((float*)C)[((((long long)bb * NH + hh) * D + dd) << 10) + ss] = v1;
                } else if (PERMOUT) {
                    ((float*)C)[row * ldc + permc(col)]     = v0;
                    ((float*)C)[row * ldc + permc(col + 1)] = v1;
                } else if (sizeof(OutT) == 2) {
                    *reinterpret_cast<__half2*>((__half*)C + row * ldc + col) =
                        __floats2half2_rn(v0, v1);
                } else {
                    *reinterpret_cast<float2*>((float*)C + row * ldc + col) =
                        make_float2(v0, v1);
                }
            }
        }
    }
}

// -------- merged projection kernel: 128x128 tiles, 2 CTAs/SM --------
// q,k,posk,posq written K-permuted; v written plain (vT scatter).
__global__ void __launch_bounds__(256, 2) k_proj(
    const float* __restrict__ hs, const float* __restrict__ rel,
    const float* __restrict__ Wq, const float* __restrict__ bq,
    const float* __restrict__ Wk, const float* __restrict__ bk,
    const float* __restrict__ Wv, const float* __restrict__ bv)
{
    int y = blockIdx.y;
    int col0 = blockIdx.x * 128;
    if (y < 32)
        gemm_body<1, 128, 128, true, true, true, false, true>(hs, HID, Wq, HID, bq, nullptr, 0, g_q, HID, HID, y * 128, col0);
    else if (y < 64)
        gemm_body<1, 128, 128, true, true, true, false, true>(hs, HID, Wk, HID, bk, nullptr, 0, g_k, HID, HID, (y - 32) * 128, col0);
    else if (y < 96)
        gemm_body<3, 128, 128, true, true, true, false, false>(hs, HID, Wv, HID, bv, nullptr, 0, g_v, HID, HID, (y - 64) * 128, col0);
    else if (y < 100)
        gemm_body<1, 128, 128, true, true, true, false, true>(rel, HID, Wk, HID, bk, nullptr, 0, g_posk, HID, HID, (y - 96) * 128, col0);
    else
        gemm_body<1, 128, 128, true, true, true, false, true>(rel, HID, Wq, HID, bq, nullptr, 0, g_posq, HID, HID, (y - 100) * 128, col0);
}

// -------- pos-att: operands K-permuted -> PERM paired loads; fp16 outputs --------
__global__ void __launch_bounds__(256, 2) k_posatt() {
    int z = blockIdx.x;
    if (z < 1536) {
        int h = z >> 7, r = z & 127;
        gemm_body<0, 128, 128, false, false, false, true, false>(g_q + h * D, HID, g_posk + h * D, HID, nullptr, nullptr, 0,
                          g_c2p + (size_t)h * BS * POS, POS, D,
                          (r >> 2) * 128, (r & 3) * 128);
    } else {
        z -= 1536;
        int h = z >> 7, r = z & 127;
        gemm_body<0, 128, 128, false, false, false, true, false>(g_posq + h * D, HID, g_k + h * D, HID, nullptr, nullptr, 0,
                          g_p2cT + (size_t)h * POS * BS, BS, D,
                          (r >> 5) * 128, (r & 31) * 128);
    }
}

// ======== FUSED scores + in-loop gathers + softmax -> probs ========
// 512 threads = 16 warps (2 m x 8 n). CTA tile: 32 rows x 1024 cols.
// q/k K-permuted -> paired 64-bit fragment loads. 6-slot ring, 2 chunks/barrier.
__global__ void __launch_bounds__(512, 1) k_fused_scores(float* __restrict__ probs) {
    extern __shared__ float dyn[];
    float* Qs    = dyn;                       // [32][68]
    float* Ks    = Qs + 32 * 68;              // [6][64][68] ring
    float* red_m = Ks + 6 * 64 * 68;          // [32][8]
    float* red_s = red_m + 256;               // [32][8]

    int s0 = blockIdx.x * 32;
    int bh = blockIdx.y;
    int b = bh / NH, h = bh % NH;
    int tid = threadIdx.x;
    int w = tid >> 5, lane = tid & 31;
    int quad = lane >> 2, qt = lane & 3;
    int wm = (w >> 3) * 16;
    int wn = (w & 7) * 8;
    int nw = w & 7;

    const float* kptr = g_k + ((long long)b * SEQ) * HID + h * D;
    unsigned ks_base = (unsigned)__cvta_generic_to_shared(Ks);

    int r0 = tid >> 4, c0 = (tid & 15) << 2;
    int r1 = (tid + 512) >> 4, c1 = ((tid + 512) & 15) << 2;

    auto issue_k = [&](int cc) {
        int slot = cc % 6;
        const float* srcb = kptr + (long long)cc * 64 * HID;
        cp_async16(ks_base + (unsigned)(((slot * 64 + r0) * 68 + c0) * 4),
                   srcb + (long long)r0 * HID + c0);
        cp_async16(ks_base + (unsigned)(((slot * 64 + r1) * 68 + c1) * 4),
                   srcb + (long long)r1 * HID + c1);
        asm volatile("cp.async.commit_group;\n");
    };

    issue_k(0); issue_k(1); issue_k(2); issue_k(3);

    {
        int m = tid >> 4, kq = (tid & 15) * 4;
        *reinterpret_cast<float4*>(&Qs[m * 68 + kq]) =
            *reinterpret_cast<const float4*>(
                g_q + ((long long)(b * SEQ + s0 + m)) * HID + h * D + kq);
    }
    __syncthreads();

    // hoist q fragments via paired loads (K-permuted layout)
    unsigned areg[8][4];
#pragma unroll
    for (int ks = 0; ks < 8; ks++) {
        int kk = ks * 8;
        float2 a0 = *reinterpret_cast<const float2*>(&Qs[(wm + quad) * 68 + kk + 2 * qt]);
        float2 a1 = *reinterpret_cast<const float2*>(&Qs[(wm + quad + 8) * 68 + kk + 2 * qt]);
        areg[ks][0] = __float_as_uint(a0.x);
        areg[ks][1] = __float_as_uint(a1.x);
        areg[ks][2] = __float_as_uint(a0.y);
        areg[ks][3] = __float_as_uint(a1.y);
    }

    float acc[16][4];
#pragma unroll
    for (int f = 0; f < 16; f++)
#pragma unroll
        for (int j = 0; j < 4; j++) acc[f][j] = 0.0f;

    const float inv = rsqrtf(192.0f);
    int sl0 = wm + quad;
    long long c2pb0 = ((long long)h * BS + b * SEQ + s0 + sl0) * POS;
    long long c2pb1 = c2pb0 + 8LL * POS;
    long long pTb = (long long)h * POS * BS + (long long)b * SEQ;
    float rmax[2] = {-1e30f, -1e30f};

    auto do_chunk = [&](int c) {
        int slot = c % 6;
        const float* kb = &Ks[(slot * 64 + wn + quad) * 68];
#pragma unroll
        for (int ks = 0; ks < 8; ks++) {
            float2 bp = *reinterpret_cast<const float2*>(&kb[ks * 8 + 2 * qt]);
            unsigned bb[2];
            bb[0] = __float_as_uint(bp.x);
            bb[1] = __float_as_uint(bp.y);
            mma_tf32(acc[c], areg[ks], bb);
        }
        int colb = c * 64 + wn + qt * 2;
#pragma unroll
        for (int rh = 0; rh < 2; rh++) {
            int s = s0 + sl0 + rh * 8;
            long long cb = rh ? c2pb1 : c2pb0;
#pragma unroll
            for (int e = 0; e < 2; e++) {
                int t = colb + e;
                int ci = __ldg(&g_c2pidx[s - t + 1023]);
                float x = acc[c][rh * 2 + e]
                        + __half2float(__ldg(&g_c2p[cb + ci]))
                        + __half2float(__ldg(&g_p2cT[pTb + (long long)ci * BS + t]));
                x *= inv;
                acc[c][rh * 2 + e] = x;
                rmax[rh] = fmaxf(rmax[rh], x);
            }
        }
    };

#pragma unroll
    for (int c = 0; c < 16; c += 2) {
        asm volatile("cp.async.wait_group %0;\n" :: "n"(2));
        __syncthreads();
        if (c + 4 < 16) issue_k(c + 4);
        else            asm volatile("cp.async.commit_group;\n");
        if (c + 5 < 16) issue_k(c + 5);
        else            asm volatile("cp.async.commit_group;\n");
        do_chunk(c);
        do_chunk(c + 1);
    }

#pragma unroll
    for (int o = 1; o <= 2; o <<= 1) {
        rmax[0] = fmaxf(rmax[0], __shfl_xor_sync(0xffffffffu, rmax[0], o));
        rmax[1] = fmaxf(rmax[1], __shfl_xor_sync(0xffffffffu, rmax[1], o));
    }
    if (qt == 0) { red_m[sl0 * 8 + nw] = rmax[0]; red_m[(sl0 + 8) * 8 + nw] = rmax[1]; }
    __syncthreads();
    float mrow[2];
#pragma unroll
    for (int rh = 0; rh < 2; rh++) {
        float m = red_m[(sl0 + rh * 8) * 8];
#pragma unroll
        for (int j = 1; j < 8; j++) m = fmaxf(m, red_m[(sl0 + rh * 8) * 8 + j]);
        mrow[rh] = m;
    }
    float rsum[2] = {0.0f, 0.0f};
#pragma unroll
    for (int f = 0; f < 16; f++)
#pragma unroll
        for (int rh = 0; rh < 2; rh++)
#pragma unroll
            for (int e = 0; e < 2; e++) {
                float v = __expf(acc[f][rh * 2 + e] - mrow[rh]);
                acc[f][rh * 2 + e] = v;
                rsum[rh] += v;
            }
#pragma unroll
    for (int o = 1; o <= 2; o <<= 1) {
        rsum[0] += __shfl_xor_sync(0xffffffffu, rsum[0], o);
        rsum[1] += __shfl_xor_sync(0xffffffffu, rsum[1], o);
    }
    if (qt == 0) { red_s[sl0 * 8 + nw] = rsum[0]; red_s[(sl0 + 8) * 8 + nw] = rsum[1]; }
    __syncthreads();
    float rinv[2];
#pragma unroll
    for (int rh = 0; rh < 2; rh++) {
        float sum = 0.0f;
#pragma unroll
        for (int j = 0; j < 8; j++) sum += red_s[(sl0 + rh * 8) * 8 + j];
        rinv[rh] = 1.0f / sum;
    }
#pragma unroll
    for (int rh = 0; rh < 2; rh++) {
        float* prow = probs + ((long long)bh * SEQ + s0 + sl0 + rh * 8) * SEQ;
#pragma unroll
        for (int f = 0; f < 16; f++) {
            int colb = f * 64 + wn + qt * 2;
            *reinterpret_cast<float2*>(&prow[colb]) =
                make_float2(acc[f][rh * 2] * rinv[rh], acc[f][rh * 2 + 1] * rinv[rh]);
        }
    }
}

// ctx = probs @ vT, 2 CTAs/SM (v/probs unpermuted in their K-dim = t)
__global__ void __launch_bounds__(256, 2) k_ctx(const float* __restrict__ probs) {
    int z = blockIdx.y;
    int b = z / NH, h = z % NH;
    gemm_body<0, 128, 64, true, false, true, false, false>(probs + (size_t)z * SEQ * SEQ, SEQ,
                     g_v + (size_t)z * D * SEQ, SEQ,
                     nullptr, nullptr, 0,
                     g_ctx + (size_t)(b * SEQ) * HID + h * D, HID, SEQ,
                     blockIdx.x * 128, 0);
}

__global__ void __launch_bounds__(256, 2) k_out(const float* __restrict__ hs,
                                                const float* __restrict__ Wo, const float* __restrict__ bo) {
    gemm_body<2, 128, 128, false, true, false, false, false>(g_ctx, HID, Wo, HID, bo, hs, HID, g_pre, HID, HID,
                      blockIdx.y * 128, blockIdx.x * 128);
}

// -------- layernorm over rows of g_pre --------
__global__ void ln_kernel(const float* __restrict__ lnw, const float* __restrict__ lnb,
                          float* __restrict__ out) {
    int row = blockIdx.x;
    const float* x = g_pre + (long long)row * HID;
    float* o = out + (long long)row * HID;
    int tid = threadIdx.x;
    __shared__ float red[8];
    float v[3];
    float s = 0.0f;
#pragma unroll
    for (int k = 0; k < 3; k++) {
        v[k] = x[tid + k * 256];
        s += v[k];
    }
#pragma unroll
    for (int o2 = 16; o2; o2 >>= 1) s += __shfl_xor_sync(0xffffffffu, s, o2);
    if ((tid & 31) == 0) red[tid >> 5] = s;
    __syncthreads();
    if (tid == 0) {
        float x2 = 0.0f;
#pragma unroll
        for (int i = 0; i < 8; i++) x2 += red[i];
        red[0] = x2;
    }
    __syncthreads();
    float mu = red[0] / (float)HID;
    __syncthreads();
    float sq = 0.0f;
#pragma unroll
    for (int k = 0; k < 3; k++) {
        float d = v[k] - mu;
        sq += d * d;
    }
#pragma unroll
    for (int o2 = 16; o2; o2 >>= 1) sq += __shfl_xor_sync(0xffffffffu, sq, o2);
    if ((tid & 31) == 0) red[tid >> 5] = sq;
    __syncthreads();
    if (tid == 0) {
        float x2 = 0.0f;
#pragma unroll
        for (int i = 0; i < 8; i++) x2 += red[i];
        red[0] = x2;
    }
    __syncthreads();
    float var = red[0] / (float)HID;
    float rstd = 1.0f / sqrtf(var + 1e-7f);
#pragma unroll
    for (int k = 0; k < 3; k++) {
        int c = tid + k * 256;
        o[c] = lnw[c] * (v[k] - mu) * rstd + lnb[c];
    }
}

extern "C" void kernel_launch(void* const* d_in, const int* in_sizes, int n_in,
                              void* d_out, int out_size) {
    const float* hs  = (const float*)d_in[0];
    const float* rel = (const float*)d_in[1];
    const float* Wq  = (const float*)d_in[2];
    const float* bq  = (const float*)d_in[3];
    const float* Wk  = (const float*)d_in[4];
    const float* bk  = (const float*)d_in[5];
    const float* Wv  = (const float*)d_in[6];
    const float* bv  = (const float*)d_in[7];
    const float* Wo  = (const float*)d_in[8];
    const float* bo  = (const float*)d_in[9];
    const float* lnw = (const float*)d_in[10];
    const float* lnb = (const float*)d_in[11];

    float* out   = (float*)d_out;
    float* probs = out + (size_t)BS * HID;

    const int GEMM_N128_SMEM = 4 * 256 * 20 * 4;  // 81920
    const int GEMM_N64_SMEM  = 4 * 192 * 20 * 4;  // 61440
    const int FUSED_SMEM = (32 * 68 + 6 * 64 * 68 + 512) * 4;  // 115200

    cudaFuncSetAttribute(k_proj,   cudaFuncAttributeMaxDynamicSharedMemorySize, GEMM_N128_SMEM);
    cudaFuncSetAttribute(k_posatt, cudaFuncAttributeMaxDynamicSharedMemorySize, GEMM_N128_SMEM);
    cudaFuncSetAttribute(k_out,    cudaFuncAttributeMaxDynamicSharedMemorySize, GEMM_N128_SMEM);
    cudaFuncSetAttribute(k_ctx,    cudaFuncAttributeMaxDynamicSharedMemorySize, GEMM_N64_SMEM);
    cudaFuncSetAttribute(k_fused_scores, cudaFuncAttributeMaxDynamicSharedMemorySize, FUSED_SMEM);

    relb_kernel<<<8, 256>>>();
    k_proj<<<dim3(HID / 128, 104), 256, GEMM_N128_SMEM>>>(hs, rel, Wq, bq, Wk, bk, Wv, bv);
    k_posatt<<<3072, 256, GEMM_N128_SMEM>>>();
    k_fused_scores<<<dim3(SEQ / 32, BAT * NH), 512, FUSED_SMEM>>>(probs);
    k_ctx<<<dim3(SEQ / 128, BAT * NH), 256, GEMM_N64_SMEM>>>(probs);
    k_out<<<dim3(HID / 128, BS / 128), 256, GEMM_N128_SMEM>>>(hs, Wo, bo);
    ln_kernel<<<BS, 256>>>(lnw, lnb, out);
}

// round 14
// speedup vs baseline: 1.0347x; 1.0347x over previous
#include <cuda_runtime.h>
#include <cuda_fp16.h>
#include <math.h>

#define NH   12
#define D    64
#define SEQ  1024
#define BAT  4
#define HID  768
#define BS   4096      // BAT*SEQ
#define POS  512       // 2*span
#define SPAN 256

// -------- scratch (static device memory; no allocations) --------
__device__ float  g_q[BS * HID];                   // tf32-rounded
__device__ float  g_k[BS * HID];                   // tf32-rounded
__device__ float  g_v[BS * HID];                   // tf32-rounded, [b][h][d][s]
__device__ float  g_ctx[BS * HID];                 // tf32-rounded
__device__ float  g_pre[BS * HID];
__device__ float  g_posk[POS * HID];               // tf32-rounded
__device__ float  g_posq[POS * HID];               // tf32-rounded
__device__ __half g_c2p[(size_t)NH * BS * POS];    // [h][b*S+s][512] fp16
__device__ __half g_p2cT[(size_t)NH * POS * BS];   // [h][bucket][b*S+t] fp16
__device__ int    g_c2pidx[2048];

// -------- relative-position bucket table (matches numpy exactly) --------
// p2c's gather index equals c2p's (log-bucket map is odd-symmetric); one table.
__global__ void relb_kernel() {
    int i = blockIdx.x * blockDim.x + threadIdx.x;
    if (i >= 2047) return;
    int rel = i - 1023;
    const int mid = 128;
    int sgn = (rel > 0) - (rel < 0);
    float abs_pos = (rel < mid && rel > -mid) ? (float)(mid - 1) : (float)abs(rel);
    float num32 = logf(abs_pos / 128.0f);
    double log_pos = ceil((double)num32 / log(511.0 / 128.0) * 127.0) + 128.0;
    long long bucket = (abs_pos <= 128.0f) ? (long long)rel
                                           : (long long)(log_pos * (double)sgn);
    int bi = (int)bucket;
    int c = bi + SPAN;  c = c < 0 ? 0 : (c > 2 * SPAN - 1 ? 2 * SPAN - 1 : c);
    g_c2pidx[i] = c;
}

// -------- tf32 helpers --------
__device__ __forceinline__ float f2tf(float x) {
    unsigned u;
    asm("cvt.rna.tf32.f32 %0, %1;" : "=r"(u) : "f"(x));
    return __uint_as_float(u);
}
__device__ __forceinline__ unsigned f2tfu(float x) {
    unsigned u;
    asm("cvt.rna.tf32.f32 %0, %1;" : "=r"(u) : "f"(x));
    return u;
}

__device__ __forceinline__ void mma_tf32(float* c, const unsigned* a, const unsigned* b) {
    asm volatile(
        "mma.sync.aligned.m16n8k8.row.col.f32.tf32.tf32.f32 "
        "{%0,%1,%2,%3},{%4,%5,%6,%7},{%8,%9},{%0,%1,%2,%3};"
        : "+f"(c[0]), "+f"(c[1]), "+f"(c[2]), "+f"(c[3])
        : "r"(a[0]), "r"(a[1]), "r"(a[2]), "r"(a[3]), "r"(b[0]), "r"(b[1]));
}

__device__ __forceinline__ void cp_async16(unsigned dst, const void* src) {
    asm volatile("cp.async.cg.shared.global [%0], [%1], 16;\n" :: "r"(dst), "l"(src));
}

// ======== generic NT GEMM with 4-stage cp.async ring (R12 version) ========
template<int EPI, int TM, int TN, bool CVTA, bool CVTB, bool RND, typename OutT>
__device__ __forceinline__ void gemm_body(
    const float* __restrict__ A, int lda,
    const float* __restrict__ B, int ldb,
    const float* __restrict__ bias,
    const float* __restrict__ resid, int ldr,
    OutT* __restrict__ C, long long ldc, int K,
    int row0, int col0)
{
    constexpr int MI = 2;
    constexpr int NI = (TN == 64) ? 4 : 8;
    constexpr int ROWS = TM + TN;
    constexpr int CP = ROWS / 64;
    extern __shared__ float S[];          // [4][ROWS][20]
    int tid = threadIdx.x;
    int wid = tid >> 5, lane = tid & 31;
    int quad = lane >> 2, qt = lane & 3;
    int wm, wn;
    if (TN == 64) { wm = (wid >> 1) * 32; wn = (wid & 1) * 32; }
    else          { wm = (wid & 3) * 32;  wn = (wid >> 2) * 64; }

    const float* gsrc[CP];
    unsigned soff[CP];
    unsigned sbase = (unsigned)__cvta_generic_to_shared(S);
#pragma unroll
    for (int j = 0; j < CP; j++) {
        int lin = tid + j * 256;
        int row = lin >> 2, c4 = (lin & 3) * 4;
        soff[j] = row * 20 + c4;
        gsrc[j] = (row < TM) ? A + (long long)(row0 + row) * lda + c4
                             : B + (long long)(col0 + row - TM) * ldb + c4;
    }
    auto issue = [&](int cc) {
        int slot = cc & 3;
        long long k0 = (long long)cc * 16;
#pragma unroll
        for (int j = 0; j < CP; j++)
            cp_async16(sbase + (slot * ROWS * 20 + soff[j]) * 4, gsrc[j] + k0);
        asm volatile("cp.async.commit_group;\n");
    };

    float acc[MI][NI][4];
#pragma unroll
    for (int i = 0; i < MI; i++)
#pragma unroll
        for (int j = 0; j < NI; j++)
#pragma unroll
            for (int l = 0; l < 4; l++) acc[i][j][l] = 0.0f;

    auto ldA = [&](const float* p) -> unsigned {
        return CVTA ? f2tfu(*p) : __float_as_uint(*p);
    };
    auto ldB = [&](const float* p) -> unsigned {
        return CVTB ? f2tfu(*p) : __float_as_uint(*p);
    };

    auto comp = [&](int slot) {
        const float* Sb = S + slot * ROWS * 20;
#pragma unroll
        for (int kk = 0; kk < 16; kk += 8) {
            unsigned af[MI][4], bfr[NI][2];
#pragma unroll
            for (int mi = 0; mi < MI; mi++) {
                int r = wm + mi * 16 + quad;
                af[mi][0] = ldA(&Sb[r * 20 + kk + qt]);
                af[mi][1] = ldA(&Sb[(r + 8) * 20 + kk + qt]);
                af[mi][2] = ldA(&Sb[r * 20 + kk + qt + 4]);
                af[mi][3] = ldA(&Sb[(r + 8) * 20 + kk + qt + 4]);
            }
#pragma unroll
            for (int ni = 0; ni < NI; ni++) {
                int n = TM + wn + ni * 8 + quad;
                bfr[ni][0] = ldB(&Sb[n * 20 + kk + qt]);
                bfr[ni][1] = ldB(&Sb[n * 20 + kk + qt + 4]);
            }
#pragma unroll
            for (int mi = 0; mi < MI; mi++)
#pragma unroll
                for (int ni = 0; ni < NI; ni++)
                    mma_tf32(acc[mi][ni], af[mi], bfr[ni]);
        }
    };

    int nst = K >> 4;
    issue(0); issue(1); issue(2);
    for (int c = 0; c < nst; c++) {
        asm volatile("cp.async.wait_group %0;\n" :: "n"(2));
        __syncthreads();
        if (c + 3 < nst) issue(c + 3);
        else asm volatile("cp.async.commit_group;\n");
        comp(c & 3);
    }

    // epilogue
#pragma unroll
    for (int mi = 0; mi < MI; mi++) {
#pragma unroll
        for (int half = 0; half < 2; half++) {
            long long row = row0 + wm + mi * 16 + quad + half * 8;
#pragma unroll
            for (int ni = 0; ni < NI; ni++) {
                long long col = col0 + wn + ni * 8 + qt * 2;
                float v0 = acc[mi][ni][half * 2 + 0];
                float v1 = acc[mi][ni][half * 2 + 1];
                if (EPI >= 1) { v0 += bias[col]; v1 += bias[col + 1]; }
                if (EPI == 2) {
                    v0 += resid[row * ldr + col];
                    v1 += resid[row * ldr + col + 1];
                }
                if (RND) { v0 = f2tf(v0); v1 = f2tf(v1); }
                if (EPI == 3) {
                    int bb = (int)(row >> 10), ss = (int)(row & 1023);
                    int hh = (int)(col >> 6), dd = (int)(col & 63);
                    ((float*)C)[((((long long)bb * NH + hh) * D + dd) << 10) + ss] = v0;
                    hh = (int)((col + 1) >> 6); dd = (int)((col + 1) & 63);
                    ((float*)C)[((((long long)bb * NH + hh) * D + dd) << 10) + ss] = v1;
                } else if (sizeof(OutT) == 2) {
                    *reinterpret_cast<__half2*>((__half*)C + row * ldc + col) =
                        __floats2half2_rn(v0, v1);
                } else {
                    *reinterpret_cast<float2*>((float*)C + row * ldc + col) =
                        make_float2(v0, v1);
                }
            }
        }
    }
}

// -------- merged projection kernel: 128x128 tiles, 2 CTAs/SM --------
__global__ void __launch_bounds__(256, 2) k_proj(
    const float* __restrict__ hs, const float* __restrict__ rel,
    const float* __restrict__ Wq, const float* __restrict__ bq,
    const float* __restrict__ Wk, const float* __restrict__ bk,
    const float* __restrict__ Wv, const float* __restrict__ bv)
{
    int y = blockIdx.y;
    int col0 = blockIdx.x * 128;
    if (y < 32)
        gemm_body<1, 128, 128, true, true, true>(hs, HID, Wq, HID, bq, nullptr, 0, g_q, HID, HID, y * 128, col0);
    else if (y < 64)
        gemm_body<1, 128, 128, true, true, true>(hs, HID, Wk, HID, bk, nullptr, 0, g_k, HID, HID, (y - 32) * 128, col0);
    else if (y < 96)
        gemm_body<3, 128, 128, true, true, true>(hs, HID, Wv, HID, bv, nullptr, 0, g_v, HID, HID, (y - 64) * 128, col0);
    else if (y < 100)
        gemm_body<1, 128, 128, true, true, true>(rel, HID, Wk, HID, bk, nullptr, 0, g_posk, HID, HID, (y - 96) * 128, col0);
    else
        gemm_body<1, 128, 128, true, true, true>(rel, HID, Wq, HID, bq, nullptr, 0, g_posq, HID, HID, (y - 100) * 128, col0);
}

// -------- pos-att: c2p [h][s][bucket] and p2cT [h][bucket][t], fp16, 2 CTAs/SM --------
__global__ void __launch_bounds__(256, 2) k_posatt() {
    int z = blockIdx.x;
    if (z < 1536) {
        int h = z >> 7, r = z & 127;
        gemm_body<0, 128, 128, false, false, false>(g_q + h * D, HID, g_posk + h * D, HID, nullptr, nullptr, 0,
                          g_c2p + (size_t)h * BS * POS, POS, D,
                          (r >> 2) * 128, (r & 3) * 128);
    } else {
        z -= 1536;
        int h = z >> 7, r = z & 127;
        gemm_body<0, 128, 128, false, false, false>(g_posq + h * D, HID, g_k + h * D, HID, nullptr, nullptr, 0,
                          g_p2cT + (size_t)h * POS * BS, BS, D,
                          (r >> 5) * 128, (r & 31) * 128);
    }
}

// ======== FUSED scores + in-loop gathers + softmax -> probs ========
// 512 threads = 16 warps (2 m x 8 n). CTA tile: 32 rows x 1024 cols.
// 12-slot cp.async ring, 4 chunks per barrier (prefetch depth 8).
__global__ void __launch_bounds__(512, 1) k_fused_scores(float* __restrict__ probs) {
    extern __shared__ float dyn[];
    float* Qs    = dyn;                       // [32][68]
    float* Ks    = Qs + 32 * 68;              // [12][64][68] ring
    float* red_m = Ks + 12 * 64 * 68;         // [32][8]
    float* red_s = red_m + 256;               // [32][8]

    int s0 = blockIdx.x * 32;
    int bh = blockIdx.y;
    int b = bh / NH, h = bh % NH;
    int tid = threadIdx.x;
    int w = tid >> 5, lane = tid & 31;
    int quad = lane >> 2, qt = lane & 3;
    int wm = (w >> 3) * 16;
    int wn = (w & 7) * 8;
    int nw = w & 7;

    const float* kptr = g_k + ((long long)b * SEQ) * HID + h * D;
    unsigned ks_base = (unsigned)__cvta_generic_to_shared(Ks);

    int r0 = tid >> 4, c0 = (tid & 15) << 2;
    int r1 = (tid + 512) >> 4, c1 = ((tid + 512) & 15) << 2;

    auto issue_k = [&](int cc) {
        int slot = cc % 12;
        const float* srcb = kptr + (long long)cc * 64 * HID;
        cp_async16(ks_base + (unsigned)(((slot * 64 + r0) * 68 + c0) * 4),
                   srcb + (long long)r0 * HID + c0);
        cp_async16(ks_base + (unsigned)(((slot * 64 + r1) * 68 + c1) * 4),
                   srcb + (long long)r1 * HID + c1);
        asm volatile("cp.async.commit_group;\n");
    };

    // prologue: 8 chunks in flight
#pragma unroll
    for (int c = 0; c < 8; c++) issue_k(c);

    {
        int m = tid >> 4, kq = (tid & 15) * 4;
        *reinterpret_cast<float4*>(&Qs[m * 68 + kq]) =
            *reinterpret_cast<const float4*>(
                g_q + ((long long)(b * SEQ + s0 + m)) * HID + h * D + kq);
    }
    __syncthreads();

    unsigned areg[8][4];
#pragma unroll
    for (int ks = 0; ks < 8; ks++) {
        int kk = ks * 8;
        areg[ks][0] = __float_as_uint(Qs[(wm + quad) * 68 + kk + qt]);
        areg[ks][1] = __float_as_uint(Qs[(wm + quad + 8) * 68 + kk + qt]);
        areg[ks][2] = __float_as_uint(Qs[(wm + quad) * 68 + kk + qt + 4]);
        areg[ks][3] = __float_as_uint(Qs[(wm + quad + 8) * 68 + kk + qt + 4]);
    }

    float acc[16][4];
#pragma unroll
    for (int f = 0; f < 16; f++)
#pragma unroll
        for (int j = 0; j < 4; j++) acc[f][j] = 0.0f;

    const float inv = rsqrtf(192.0f);
    int sl0 = wm + quad;
    long long c2pb0 = ((long long)h * BS + b * SEQ + s0 + sl0) * POS;
    long long c2pb1 = c2pb0 + 8LL * POS;
    long long pTb = (long long)h * POS * BS + (long long)b * SEQ;
    float rmax[2] = {-1e30f, -1e30f};

    auto do_chunk = [&](int c) {
        int slot = c % 12;
        const float* kb = &Ks[(slot * 64 + wn + quad) * 68];
#pragma unroll
        for (int ks = 0; ks < 8; ks++) {
            unsigned bb[2];
            bb[0] = __float_as_uint(kb[ks * 8 + qt]);
            bb[1] = __float_as_uint(kb[ks * 8 + qt + 4]);
            mma_tf32(acc[c], areg[ks], bb);
        }
        int colb = c * 64 + wn + qt * 2;
#pragma unroll
        for (int rh = 0; rh < 2; rh++) {
            int s = s0 + sl0 + rh * 8;
            long long cb = rh ? c2pb1 : c2pb0;
#pragma unroll
            for (int e = 0; e < 2; e++) {
                int t = colb + e;
                int ci = __ldg(&g_c2pidx[s - t + 1023]);
                float x = acc[c][rh * 2 + e]
                        + __half2float(__ldg(&g_c2p[cb + ci]))
                        + __half2float(__ldg(&g_p2cT[pTb + (long long)ci * BS + t]));
                x *= inv;
                acc[c][rh * 2 + e] = x;
                rmax[rh] = fmaxf(rmax[rh], x);
            }
        }
    };

#pragma unroll
    for (int c = 0; c < 16; c += 4) {
        asm volatile("cp.async.wait_group %0;\n" :: "n"(4));
        __syncthreads();
#pragma unroll
        for (int j = 0; j < 4; j++) {
            if (c + 8 + j < 16) issue_k(c + 8 + j);
            else asm volatile("cp.async.commit_group;\n");
        }
        do_chunk(c);
        do_chunk(c + 1);
        do_chunk(c + 2);
        do_chunk(c + 3);
    }

#pragma unroll
    for (int o = 1; o <= 2; o <<= 1) {
        rmax[0] = fmaxf(rmax[0], __shfl_xor_sync(0xffffffffu, rmax[0], o));
        rmax[1] = fmaxf(rmax[1], __shfl_xor_sync(0xffffffffu, rmax[1], o));
    }
    if (qt == 0) { red_m[sl0 * 8 + nw] = rmax[0]; red_m[(sl0 + 8) * 8 + nw] = rmax[1]; }
    __syncthreads();
    float mrow[2];
#pragma unroll
    for (int rh = 0; rh < 2; rh++) {
        float m = red_m[(sl0 + rh * 8) * 8];
#pragma unroll
        for (int j = 1; j < 8; j++) m = fmaxf(m, red_m[(sl0 + rh * 8) * 8 + j]);
        mrow[rh] = m;
    }
    float rsum[2] = {0.0f, 0.0f};
#pragma unroll
    for (int f = 0; f < 16; f++)
#pragma unroll
        for (int rh = 0; rh < 2; rh++)
#pragma unroll
            for (int e = 0; e < 2; e++) {
                float v = __expf(acc[f][rh * 2 + e] - mrow[rh]);
                acc[f][rh * 2 + e] = v;
                rsum[rh] += v;
            }
#pragma unroll
    for (int o = 1; o <= 2; o <<= 1) {
        rsum[0] += __shfl_xor_sync(0xffffffffu, rsum[0], o);
        rsum[1] += __shfl_xor_sync(0xffffffffu, rsum[1], o);
    }
    if (qt == 0) { red_s[sl0 * 8 + nw] = rsum[0]; red_s[(sl0 + 8) * 8 + nw] = rsum[1]; }
    __syncthreads();
    float rinv[2];
#pragma unroll
    for (int rh = 0; rh < 2; rh++) {
        float sum = 0.0f;
#pragma unroll
        for (int j = 0; j < 8; j++) sum += red_s[(sl0 + rh * 8) * 8 + j];
        rinv[rh] = 1.0f / sum;
    }
#pragma unroll
    for (int rh = 0; rh < 2; rh++) {
        float* prow = probs + ((long long)bh * SEQ + s0 + sl0 + rh * 8) * SEQ;
#pragma unroll
        for (int f = 0; f < 16; f++) {
            int colb = f * 64 + wn + qt * 2;
            *reinterpret_cast<float2*>(&prow[colb]) =
                make_float2(acc[f][rh * 2] * rinv[rh], acc[f][rh * 2 + 1] * rinv[rh]);
        }
    }
}

// ctx = probs @ vT, 2 CTAs/SM
__global__ void __launch_bounds__(256, 2) k_ctx(const float* __restrict__ probs) {
    int z = blockIdx.y;
    int b = z / NH, h = z % NH;
    gemm_body<0, 128, 64, true, false, true>(probs + (size_t)z * SEQ * SEQ, SEQ,
                     g_v + (size_t)z * D * SEQ, SEQ,
                     nullptr, nullptr, 0,
                     g_ctx + (size_t)(b * SEQ) * HID + h * D, HID, SEQ,
                     blockIdx.x * 128, 0);
}

__global__ void __launch_bounds__(256, 2) k_out(const float* __restrict__ hs,
                                                const float* __restrict__ Wo, const float* __restrict__ bo) {
    gemm_body<2, 128, 128, false, true, false>(g_ctx, HID, Wo, HID, bo, hs, HID, g_pre, HID, HID,
                      blockIdx.y * 128, blockIdx.x * 128);
}

// -------- layernorm over rows of g_pre --------
__global__ void ln_kernel(const float* __restrict__ lnw, const float* __restrict__ lnb,
                          float* __restrict__ out) {
    int row = blockIdx.x;
    const float* x = g_pre + (long long)row * HID;
    float* o = out + (long long)row * HID;
    int tid = threadIdx.x;
    __shared__ float red[8];
    float v[3];
    float s = 0.0f;
#pragma unroll
    for (int k = 0; k < 3; k++) {
        v[k] = x[tid + k * 256];
        s += v[k];
    }
#pragma unroll
    for (int o2 = 16; o2; o2 >>= 1) s += __shfl_xor_sync(0xffffffffu, s, o2);
    if ((tid & 31) == 0) red[tid >> 5] = s;
    __syncthreads();
    if (tid == 0) {
        float x2 = 0.0f;
#pragma unroll
        for (int i = 0; i < 8; i++) x2 += red[i];
        red[0] = x2;
    }
    __syncthreads();
    float mu = red[0] / (float)HID;
    __syncthreads();
    float sq = 0.0f;
#pragma unroll
    for (int k = 0; k < 3; k++) {
        float d = v[k] - mu;
        sq += d * d;
    }
#pragma unroll
    for (int o2 = 16; o2; o2 >>= 1) sq += __shfl_xor_sync(0xffffffffu, sq, o2);
    if ((tid & 31) == 0) red[tid >> 5] = sq;
    __syncthreads();
    if (tid == 0) {
        float x2 = 0.0f;
#pragma unroll
        for (int i = 0; i < 8; i++) x2 += red[i];
        red[0] = x2;
    }
    __syncthreads();
    float var = red[0] / (float)HID;
    float rstd = 1.0f / sqrtf(var + 1e-7f);
#pragma unroll
    for (int k = 0; k < 3; k++) {
        int c = tid + k * 256;
        o[c] = lnw[c] * (v[k] - mu) * rstd + lnb[c];
    }
}

extern "C" void kernel_launch(void* const* d_in, const int* in_sizes, int n_in,
                              void* d_out, int out_size) {
    const float* hs  = (const float*)d_in[0];
    const float* rel = (const float*)d_in[1];
    const float* Wq  = (const float*)d_in[2];
    const float* bq  = (const float*)d_in[3];
    const float* Wk  = (const float*)d_in[4];
    const float* bk  = (const float*)d_in[5];
    const float* Wv  = (const float*)d_in[6];
    const float* bv  = (const float*)d_in[7];
    const float* Wo  = (const float*)d_in[8];
    const float* bo  = (const float*)d_in[9];
    const float* lnw = (const float*)d_in[10];
    const float* lnb = (const float*)d_in[11];

    float* out   = (float*)d_out;
    float* probs = out + (size_t)BS * HID;

    const int GEMM_N128_SMEM = 4 * 256 * 20 * 4;  // 81920
    const int GEMM_N64_SMEM  = 4 * 192 * 20 * 4;  // 61440
    const int FUSED_SMEM = (32 * 68 + 12 * 64 * 68 + 512) * 4;  // 219648

    cudaFuncSetAttribute(k_proj,   cudaFuncAttributeMaxDynamicSharedMemorySize, GEMM_N128_SMEM);
    cudaFuncSetAttribute(k_posatt, cudaFuncAttributeMaxDynamicSharedMemorySize, GEMM_N128_SMEM);
    cudaFuncSetAttribute(k_out,    cudaFuncAttributeMaxDynamicSharedMemorySize, GEMM_N128_SMEM);
    cudaFuncSetAttribute(k_ctx,    cudaFuncAttributeMaxDynamicSharedMemorySize, GEMM_N64_SMEM);
    cudaFuncSetAttribute(k_fused_scores, cudaFuncAttributeMaxDynamicSharedMemorySize, FUSED_SMEM);

    relb_kernel<<<8, 256>>>();
    k_proj<<<dim3(HID / 128, 104), 256, GEMM_N128_SMEM>>>(hs, rel, Wq, bq, Wk, bk, Wv, bv);
    k_posatt<<<3072, 256, GEMM_N128_SMEM>>>();
    k_fused_scores<<<dim3(SEQ / 32, BAT * NH), 512, FUSED_SMEM>>>(probs);
    k_ctx<<<dim3(SEQ / 128, BAT * NH), 256, GEMM_N64_SMEM>>>(probs);
    k_out<<<dim3(HID / 128, BS / 128), 256, GEMM_N128_SMEM>>>(hs, Wo, bo);
    ln_kernel<<<BS, 256>>>(lnw, lnb, out);
}

// round 15
// speedup vs baseline: 1.1454x; 1.1070x over previous
#include <cuda_runtime.h>
#include <cuda_fp16.h>
#include <math.h>

#define NH   12
#define D    64
#define SEQ  1024
#define BAT  4
#define HID  768
#define BS   4096      // BAT*SEQ
#define POS  512       // 2*span
#define SPAN 256

// -------- scratch (static device memory; no allocations) --------
__device__ __half g_q[BS * HID];                   // fp16
__device__ __half g_k[BS * HID];                   // fp16
__device__ float  g_v[BS * HID];                   // tf32-rounded, [b][h][d][s]
__device__ float  g_ctx[BS * HID];                 // tf32-rounded
__device__ float  g_pre[BS * HID];
__device__ __half g_posk[POS * HID];               // fp16
__device__ __half g_posq[POS * HID];               // fp16
__device__ __half g_c2p[(size_t)NH * BS * POS];    // [h][b*S+s][512] fp16
__device__ __half g_p2cT[(size_t)NH * POS * BS];   // [h][bucket][b*S+t] fp16
__device__ int    g_c2pidx[2048];

// -------- relative-position bucket table (matches numpy exactly) --------
// p2c's gather index equals c2p's (log-bucket map is odd-symmetric); one table.
__global__ void relb_kernel() {
    int i = blockIdx.x * blockDim.x + threadIdx.x;
    if (i >= 2047) return;
    int rel = i - 1023;
    const int mid = 128;
    int sgn = (rel > 0) - (rel < 0);
    float abs_pos = (rel < mid && rel > -mid) ? (float)(mid - 1) : (float)abs(rel);
    float num32 = logf(abs_pos / 128.0f);
    double log_pos = ceil((double)num32 / log(511.0 / 128.0) * 127.0) + 128.0;
    long long bucket = (abs_pos <= 128.0f) ? (long long)rel
                                           : (long long)(log_pos * (double)sgn);
    int bi = (int)bucket;
    int c = bi + SPAN;  c = c < 0 ? 0 : (c > 2 * SPAN - 1 ? 2 * SPAN - 1 : c);
    g_c2pidx[i] = c;
}

// -------- helpers --------
__device__ __forceinline__ float f2tf(float x) {
    unsigned u;
    asm("cvt.rna.tf32.f32 %0, %1;" : "=r"(u) : "f"(x));
    return __uint_as_float(u);
}
__device__ __forceinline__ unsigned f2tfu(float x) {
    unsigned u;
    asm("cvt.rna.tf32.f32 %0, %1;" : "=r"(u) : "f"(x));
    return u;
}

__device__ __forceinline__ void mma_tf32(float* c, const unsigned* a, const unsigned* b) {
    asm volatile(
        "mma.sync.aligned.m16n8k8.row.col.f32.tf32.tf32.f32 "
        "{%0,%1,%2,%3},{%4,%5,%6,%7},{%8,%9},{%0,%1,%2,%3};"
        : "+f"(c[0]), "+f"(c[1]), "+f"(c[2]), "+f"(c[3])
        : "r"(a[0]), "r"(a[1]), "r"(a[2]), "r"(a[3]), "r"(b[0]), "r"(b[1]));
}

__device__ __forceinline__ void mma_fp16(float* c, const unsigned* a, unsigned b0, unsigned b1) {
    asm volatile(
        "mma.sync.aligned.m16n8k16.row.col.f32.f16.f16.f32 "
        "{%0,%1,%2,%3},{%4,%5,%6,%7},{%8,%9},{%0,%1,%2,%3};"
        : "+f"(c[0]), "+f"(c[1]), "+f"(c[2]), "+f"(c[3])
        : "r"(a[0]), "r"(a[1]), "r"(a[2]), "r"(a[3]), "r"(b0), "r"(b1));
}

__device__ __forceinline__ void cp_async16(unsigned dst, const void* src) {
    asm volatile("cp.async.cg.shared.global [%0], [%1], 16;\n" :: "r"(dst), "l"(src));
}

// ======== generic fp32/tf32 NT GEMM with 4-stage cp.async ring (R12) ========
template<int EPI, int TM, int TN, bool CVTA, bool CVTB, bool RND, typename OutT>
__device__ __forceinline__ void gemm_body(
    const float* __restrict__ A, int lda,
    const float* __restrict__ B, int ldb,
    const float* __restrict__ bias,
    const float* __restrict__ resid, int ldr,
    OutT* __restrict__ C, long long ldc, int K,
    int row0, int col0)
{
    constexpr int MI = 2;
    constexpr int NI = (TN == 64) ? 4 : 8;
    constexpr int ROWS = TM + TN;
    constexpr int CP = ROWS / 64;
    extern __shared__ float S[];          // [4][ROWS][20]
    int tid = threadIdx.x;
    int wid = tid >> 5, lane = tid & 31;
    int quad = lane >> 2, qt = lane & 3;
    int wm, wn;
    if (TN == 64) { wm = (wid >> 1) * 32; wn = (wid & 1) * 32; }
    else          { wm = (wid & 3) * 32;  wn = (wid >> 2) * 64; }

    const float* gsrc[CP];
    unsigned soff[CP];
    unsigned sbase = (unsigned)__cvta_generic_to_shared(S);
#pragma unroll
    for (int j = 0; j < CP; j++) {
        int lin = tid + j * 256;
        int row = lin >> 2, c4 = (lin & 3) * 4;
        soff[j] = row * 20 + c4;
        gsrc[j] = (row < TM) ? A + (long long)(row0 + row) * lda + c4
                             : B + (long long)(col0 + row - TM) * ldb + c4;
    }
    auto issue = [&](int cc) {
        int slot = cc & 3;
        long long k0 = (long long)cc * 16;
#pragma unroll
        for (int j = 0; j < CP; j++)
            cp_async16(sbase + (slot * ROWS * 20 + soff[j]) * 4, gsrc[j] + k0);
        asm volatile("cp.async.commit_group;\n");
    };

    float acc[MI][NI][4];
#pragma unroll
    for (int i = 0; i < MI; i++)
#pragma unroll
        for (int j = 0; j < NI; j++)
#pragma unroll
            for (int l = 0; l < 4; l++) acc[i][j][l] = 0.0f;

    auto ldA = [&](const float* p) -> unsigned {
        return CVTA ? f2tfu(*p) : __float_as_uint(*p);
    };
    auto ldB = [&](const float* p) -> unsigned {
        return CVTB ? f2tfu(*p) : __float_as_uint(*p);
    };

    auto comp = [&](int slot) {
        const float* Sb = S + slot * ROWS * 20;
#pragma unroll
        for (int kk = 0; kk < 16; kk += 8) {
            unsigned af[MI][4], bfr[NI][2];
#pragma unroll
            for (int mi = 0; mi < MI; mi++) {
                int r = wm + mi * 16 + quad;
                af[mi][0] = ldA(&Sb[r * 20 + kk + qt]);
                af[mi][1] = ldA(&Sb[(r + 8) * 20 + kk + qt]);
                af[mi][2] = ldA(&Sb[r * 20 + kk + qt + 4]);
                af[mi][3] = ldA(&Sb[(r + 8) * 20 + kk + qt + 4]);
            }
#pragma unroll
            for (int ni = 0; ni < NI; ni++) {
                int n = TM + wn + ni * 8 + quad;
                bfr[ni][0] = ldB(&Sb[n * 20 + kk + qt]);
                bfr[ni][1] = ldB(&Sb[n * 20 + kk + qt + 4]);
            }
#pragma unroll
            for (int mi = 0; mi < MI; mi++)
#pragma unroll
                for (int ni = 0; ni < NI; ni++)
                    mma_tf32(acc[mi][ni], af[mi], bfr[ni]);
        }
    };

    int nst = K >> 4;
    issue(0); issue(1); issue(2);
    for (int c = 0; c < nst; c++) {
        asm volatile("cp.async.wait_group %0;\n" :: "n"(2));
        __syncthreads();
        if (c + 3 < nst) issue(c + 3);
        else asm volatile("cp.async.commit_group;\n");
        comp(c & 3);
    }

    // epilogue
#pragma unroll
    for (int mi = 0; mi < MI; mi++) {
#pragma unroll
        for (int half = 0; half < 2; half++) {
            long long row = row0 + wm + mi * 16 + quad + half * 8;
#pragma unroll
            for (int ni = 0; ni < NI; ni++) {
                long long col = col0 + wn + ni * 8 + qt * 2;
                float v0 = acc[mi][ni][half * 2 + 0];
                float v1 = acc[mi][ni][half * 2 + 1];
                if (EPI >= 1) { v0 += bias[col]; v1 += bias[col + 1]; }
                if (EPI == 2) {
                    v0 += resid[row * ldr + col];
                    v1 += resid[row * ldr + col + 1];
                }
                if (RND) { v0 = f2tf(v0); v1 = f2tf(v1); }
                if (EPI == 3) {
                    int bb = (int)(row >> 10), ss = (int)(row & 1023);
                    int hh = (int)(col >> 6), dd = (int)(col & 63);
                    ((float*)C)[((((long long)bb * NH + hh) * D + dd) << 10) + ss] = v0;
                    hh = (int)((col + 1) >> 6); dd = (int)((col + 1) & 63);
                    ((float*)C)[((((long long)bb * NH + hh) * D + dd) << 10) + ss] = v1;
                } else if (sizeof(OutT) == 2) {
                    *reinterpret_cast<__half2*>((__half*)C + row * ldc + col) =
                        __floats2half2_rn(v0, v1);
                } else {
                    *reinterpret_cast<float2*>((float*)C + row * ldc + col) =
                        make_float2(v0, v1);
                }
            }
        }
    }
}

// -------- merged projection kernel: q,k,posk,posq -> fp16; v -> fp32 vT --------
__global__ void __launch_bounds__(256, 2) k_proj(
    const float* __restrict__ hs, const float* __restrict__ rel,
    const float* __restrict__ Wq, const float* __restrict__ bq,
    const float* __restrict__ Wk, const float* __restrict__ bk,
    const float* __restrict__ Wv, const float* __restrict__ bv)
{
    int y = blockIdx.y;
    int col0 = blockIdx.x * 128;
    if (y < 32)
        gemm_body<1, 128, 128, true, true, false>(hs, HID, Wq, HID, bq, nullptr, 0, g_q, HID, HID, y * 128, col0);
    else if (y < 64)
        gemm_body<1, 128, 128, true, true, false>(hs, HID, Wk, HID, bk, nullptr, 0, g_k, HID, HID, (y - 32) * 128, col0);
    else if (y < 96)
        gemm_body<3, 128, 128, true, true, true>(hs, HID, Wv, HID, bv, nullptr, 0, g_v, HID, HID, (y - 64) * 128, col0);
    else if (y < 100)
        gemm_body<1, 128, 128, true, true, false>(rel, HID, Wk, HID, bk, nullptr, 0, g_posk, HID, HID, (y - 96) * 128, col0);
    else
        gemm_body<1, 128, 128, true, true, false>(rel, HID, Wq, HID, bq, nullptr, 0, g_posq, HID, HID, (y - 100) * 128, col0);
}

// -------- pos-att fp16: single-shot K=64, 128x128 tile, fp16 in/out --------
__global__ void __launch_bounds__(256, 2) k_posatt16() {
    extern __shared__ __half SH[];           // A[128][72] + B[128][72]
    __half* As = SH;
    __half* Bs = SH + 128 * 72;
    int z = blockIdx.x;
    const __half *Aop, *Bop;
    __half* Cc;
    long long ldc;
    int row0, col0;
    if (z < 1536) {                          // c2p: q @ posk^T
        int h = z >> 7, r = z & 127;
        Aop = g_q + h * D; Bop = g_posk + h * D;
        Cc = g_c2p + (size_t)h * BS * POS; ldc = POS;
        row0 = (r >> 2) * 128; col0 = (r & 3) * 128;
    } else {                                 // p2cT: posq @ k^T
        z -= 1536;
        int h = z >> 7, r = z & 127;
        Aop = g_posq + h * D; Bop = g_k + h * D;
        Cc = g_p2cT + (size_t)h * POS * BS; ldc = BS;
        row0 = (r >> 5) * 128; col0 = (r & 31) * 128;
    }
    int tid = threadIdx.x, wid = tid >> 5, lane = tid & 31;
    int quad = lane >> 2, qt = lane & 3;
    int wm = (wid & 3) * 32, wn = (wid >> 2) * 64;
    unsigned sa = (unsigned)__cvta_generic_to_shared(As);
    unsigned sb = (unsigned)__cvta_generic_to_shared(Bs);
#pragma unroll
    for (int j = 0; j < 4; j++) {
        int lin = tid + j * 256;
        int r = lin >> 3, g = lin & 7;
        cp_async16(sa + (unsigned)(r * 72 + g * 8) * 2, Aop + (long long)(row0 + r) * HID + g * 8);
        cp_async16(sb + (unsigned)(r * 72 + g * 8) * 2, Bop + (long long)(col0 + r) * HID + g * 8);
    }
    asm volatile("cp.async.commit_group;\ncp.async.wait_group 0;\n" ::: "memory");
    __syncthreads();

    float acc[2][8][4];
#pragma unroll
    for (int i = 0; i < 2; i++)
#pragma unroll
        for (int j = 0; j < 8; j++)
#pragma unroll
            for (int l = 0; l < 4; l++) acc[i][j][l] = 0.0f;

#pragma unroll
    for (int ks = 0; ks < 4; ks++) {
        int k0 = ks * 16;
        unsigned af[2][4];
#pragma unroll
        for (int mi = 0; mi < 2; mi++) {
            int r = wm + mi * 16 + quad;
            af[mi][0] = *reinterpret_cast<const unsigned*>(As + r * 72 + k0 + 2 * qt);
            af[mi][1] = *reinterpret_cast<const unsigned*>(As + (r + 8) * 72 + k0 + 2 * qt);
            af[mi][2] = *reinterpret_cast<const unsigned*>(As + r * 72 + k0 + 2 * qt + 8);
            af[mi][3] = *reinterpret_cast<const unsigned*>(As + (r + 8) * 72 + k0 + 2 * qt + 8);
        }
#pragma unroll
        for (int ni = 0; ni < 8; ni++) {
            const __half* bp = Bs + (wn + ni * 8 + quad) * 72 + k0 + 2 * qt;
            unsigned b0 = *reinterpret_cast<const unsigned*>(bp);
            unsigned b1 = *reinterpret_cast<const unsigned*>(bp + 8);
#pragma unroll
            for (int mi = 0; mi < 2; mi++) mma_fp16(acc[mi][ni], af[mi], b0, b1);
        }
    }
#pragma unroll
    for (int mi = 0; mi < 2; mi++)
#pragma unroll
        for (int half = 0; half < 2; half++) {
            long long row = row0 + wm + mi * 16 + quad + half * 8;
#pragma unroll
            for (int ni = 0; ni < 8; ni++) {
                long long col = col0 + wn + ni * 8 + qt * 2;
                *reinterpret_cast<__half2*>(Cc + row * ldc + col) =
                    __floats2half2_rn(acc[mi][ni][half * 2], acc[mi][ni][half * 2 + 1]);
            }
        }
}

// ======== FUSED fp16 scores + in-loop gathers + softmax -> probs ========
// 512 threads = 16 warps (2 m x 8 n). CTA tile: 32 rows x 1024 cols.
// 6-slot cp.async ring, 2 chunks per barrier. m16n8k16 fp16 MMA.
__global__ void __launch_bounds__(512, 1) k_fused_scores(float* __restrict__ probs) {
    extern __shared__ char dynb[];
    __half* Qs = (__half*)dynb;                      // [32][72]
    __half* Ks = Qs + 32 * 72;                       // [6][64][72] ring
    float* red_m = (float*)(Ks + 6 * 64 * 72);       // [32][8]
    float* red_s = red_m + 256;                      // [32][8]

    int s0 = blockIdx.x * 32;
    int bh = blockIdx.y;
    int b = bh / NH, h = bh % NH;
    int tid = threadIdx.x;
    int w = tid >> 5, lane = tid & 31;
    int quad = lane >> 2, qt = lane & 3;
    int wm = (w >> 3) * 16;
    int wn = (w & 7) * 8;
    int nw = w & 7;

    const __half* kptr = g_k + ((long long)b * SEQ) * HID + h * D;
    unsigned ks_base = (unsigned)__cvta_generic_to_shared(Ks);

    int r0 = tid >> 3, g0 = tid & 7;   // 64 rows x 8 granules, 1 cp/thread/chunk

    auto issue_k = [&](int cc) {
        int slot = cc % 6;
        cp_async16(ks_base + (unsigned)((slot * 64 + r0) * 72 + g0 * 8) * 2,
                   kptr + (long long)(cc * 64 + r0) * HID + g0 * 8);
        asm volatile("cp.async.commit_group;\n");
    };

    issue_k(0); issue_k(1); issue_k(2); issue_k(3);

    // q tile (32x64 halves): 8B per thread
    {
        int m = tid >> 4, c = (tid & 15) * 4;
        *reinterpret_cast<uint2*>(Qs + m * 72 + c) =
            *reinterpret_cast<const uint2*>(
                g_q + ((long long)(b * SEQ + s0 + m)) * HID + h * D + c);
    }
    __syncthreads();

    // hoist q fragments: 4 k16-steps x 4 regs
    unsigned areg[4][4];
#pragma unroll
    for (int ks = 0; ks < 4; ks++) {
        int k0 = ks * 16;
        areg[ks][0] = *reinterpret_cast<const unsigned*>(Qs + (wm + quad) * 72 + k0 + 2 * qt);
        areg[ks][1] = *reinterpret_cast<const unsigned*>(Qs + (wm + quad + 8) * 72 + k0 + 2 * qt);
        areg[ks][2] = *reinterpret_cast<const unsigned*>(Qs + (wm + quad) * 72 + k0 + 2 * qt + 8);
        areg[ks][3] = *reinterpret_cast<const unsigned*>(Qs + (wm + quad + 8) * 72 + k0 + 2 * qt + 8);
    }

    float acc[16][4];
#pragma unroll
    for (int f = 0; f < 16; f++)
#pragma unroll
        for (int j = 0; j < 4; j++) acc[f][j] = 0.0f;

    const float inv = rsqrtf(192.0f);
    int sl0 = wm + quad;
    long long c2pb0 = ((long long)h * BS + b * SEQ + s0 + sl0) * POS;
    long long c2pb1 = c2pb0 + 8LL * POS;
    long long pTb = (long long)h * POS * BS + (long long)b * SEQ;
    float rmax[2] = {-1e30f, -1e30f};

    auto do_chunk = [&](int c) {
        int slot = c % 6;
        const __half* kb = Ks + (slot * 64 + wn + quad) * 72;
#pragma unroll
        for (int ks = 0; ks < 4; ks++) {
            int k0 = ks * 16;
            unsigned b0 = *reinterpret_cast<const unsigned*>(kb + k0 + 2 * qt);
            unsigned b1 = *reinterpret_cast<const unsigned*>(kb + k0 + 2 * qt + 8);
            mma_fp16(acc[c], areg[ks], b0, b1);
        }
        int colb = c * 64 + wn + qt * 2;
#pragma unroll
        for (int rh = 0; rh < 2; rh++) {
            int s = s0 + sl0 + rh * 8;
            long long cb = rh ? c2pb1 : c2pb0;
#pragma unroll
            for (int e = 0; e < 2; e++) {
                int t = colb + e;
                int ci = __ldg(&g_c2pidx[s - t + 1023]);
                float x = acc[c][rh * 2 + e]
                        + __half2float(__ldg(&g_c2p[cb + ci]))
                        + __half2float(__ldg(&g_p2cT[pTb + (long long)ci * BS + t]));
                x *= inv;
                acc[c][rh * 2 + e] = x;
                rmax[rh] = fmaxf(rmax[rh], x);
            }
        }
    };

#pragma unroll
    for (int c = 0; c < 16; c += 2) {
        asm volatile("cp.async.wait_group %0;\n" :: "n"(2));
        __syncthreads();
        if (c + 4 < 16) issue_k(c + 4);
        else            asm volatile("cp.async.commit_group;\n");
        if (c + 5 < 16) issue_k(c + 5);
        else            asm volatile("cp.async.commit_group;\n");
        do_chunk(c);
        do_chunk(c + 1);
    }

#pragma unroll
    for (int o = 1; o <= 2; o <<= 1) {
        rmax[0] = fmaxf(rmax[0], __shfl_xor_sync(0xffffffffu, rmax[0], o));
        rmax[1] = fmaxf(rmax[1], __shfl_xor_sync(0xffffffffu, rmax[1], o));
    }
    if (qt == 0) { red_m[sl0 * 8 + nw] = rmax[0]; red_m[(sl0 + 8) * 8 + nw] = rmax[1]; }
    __syncthreads();
    float mrow[2];
#pragma unroll
    for (int rh = 0; rh < 2; rh++) {
        float m = red_m[(sl0 + rh * 8) * 8];
#pragma unroll
        for (int j = 1; j < 8; j++) m = fmaxf(m, red_m[(sl0 + rh * 8) * 8 + j]);
        mrow[rh] = m;
    }
    float rsum[2] = {0.0f, 0.0f};
#pragma unroll
    for (int f = 0; f < 16; f++)
#pragma unroll
        for (int rh = 0; rh < 2; rh++)
#pragma unroll
            for (int e = 0; e < 2; e++) {
                float v = __expf(acc[f][rh * 2 + e] - mrow[rh]);
                acc[f][rh * 2 + e] = v;
                rsum[rh] += v;
            }
#pragma unroll
    for (int o = 1; o <= 2; o <<= 1) {
        rsum[0] += __shfl_xor_sync(0xffffffffu, rsum[0], o);
        rsum[1] += __shfl_xor_sync(0xffffffffu, rsum[1], o);
    }
    if (qt == 0) { red_s[sl0 * 8 + nw] = rsum[0]; red_s[(sl0 + 8) * 8 + nw] = rsum[1]; }
    __syncthreads();
    float rinv[2];
#pragma unroll
    for (int rh = 0; rh < 2; rh++) {
        float sum = 0.0f;
#pragma unroll
        for (int j = 0; j < 8; j++) sum += red_s[(sl0 + rh * 8) * 8 + j];
        rinv[rh] = 1.0f / sum;
    }
#pragma unroll
    for (int rh = 0; rh < 2; rh++) {
        float* prow = probs + ((long long)bh * SEQ + s0 + sl0 + rh * 8) * SEQ;
#pragma unroll
        for (int f = 0; f < 16; f++) {
            int colb = f * 64 + wn + qt * 2;
            *reinterpret_cast<float2*>(&prow[colb]) =
                make_float2(acc[f][rh * 2] * rinv[rh], acc[f][rh * 2 + 1] * rinv[rh]);
        }
    }
}

// ctx = probs @ vT, 2 CTAs/SM (tf32)
__global__ void __launch_bounds__(256, 2) k_ctx(const float* __restrict__ probs) {
    int z = blockIdx.y;
    int b = z / NH, h = z % NH;
    gemm_body<0, 128, 64, true, false, true>(probs + (size_t)z * SEQ * SEQ, SEQ,
                     g_v + (size_t)z * D * SEQ, SEQ,
                     nullptr, nullptr, 0,
                     g_ctx + (size_t)(b * SEQ) * HID + h * D, HID, SEQ,
                     blockIdx.x * 128, 0);
}

__global__ void __launch_bounds__(256, 2) k_out(const float* __restrict__ hs,
                                                const float* __restrict__ Wo, const float* __restrict__ bo) {
    gemm_body<2, 128, 128, false, true, false>(g_ctx, HID, Wo, HID, bo, hs, HID, g_pre, HID, HID,
                      blockIdx.y * 128, blockIdx.x * 128);
}

// -------- layernorm over rows of g_pre --------
__global__ void ln_kernel(const float* __restrict__ lnw, const float* __restrict__ lnb,
                          float* __restrict__ out) {
    int row = blockIdx.x;
    const float* x = g_pre + (long long)row * HID;
    float* o = out + (long long)row * HID;
    int tid = threadIdx.x;
    __shared__ float red[8];
    float v[3];
    float s = 0.0f;
#pragma unroll
    for (int k = 0; k < 3; k++) {
        v[k] = x[tid + k * 256];
        s += v[k];
    }
#pragma unroll
    for (int o2 = 16; o2; o2 >>= 1) s += __shfl_xor_sync(0xffffffffu, s, o2);
    if ((tid & 31) == 0) red[tid >> 5] = s;
    __syncthreads();
    if (tid == 0) {
        float x2 = 0.0f;
#pragma unroll
        for (int i = 0; i < 8; i++) x2 += red[i];
        red[0] = x2;
    }
    __syncthreads();
    float mu = red[0] / (float)HID;
    __syncthreads();
    float sq = 0.0f;
#pragma unroll
    for (int k = 0; k < 3; k++) {
        float d = v[k] - mu;
        sq += d * d;
    }
#pragma unroll
    for (int o2 = 16; o2; o2 >>= 1) sq += __shfl_xor_sync(0xffffffffu, sq, o2);
    if ((tid & 31) == 0) red[tid >> 5] = sq;
    __syncthreads();
    if (tid == 0) {
        float x2 = 0.0f;
#pragma unroll
        for (int i = 0; i < 8; i++) x2 += red[i];
        red[0] = x2;
    }
    __syncthreads();
    float var = red[0] / (float)HID;
    float rstd = 1.0f / sqrtf(var + 1e-7f);
#pragma unroll
    for (int k = 0; k < 3; k++) {
        int c = tid + k * 256;
        o[c] = lnw[c] * (v[k] - mu) * rstd + lnb[c];
    }
}

extern "C" void kernel_launch(void* const* d_in, const int* in_sizes, int n_in,
                              void* d_out, int out_size) {
    const float* hs  = (const float*)d_in[0];
    const float* rel = (const float*)d_in[1];
    const float* Wq  = (const float*)d_in[2];
    const float* bq  = (const float*)d_in[3];
    const float* Wk  = (const float*)d_in[4];
    const float* bk  = (const float*)d_in[5];
    const float* Wv  = (const float*)d_in[6];
    const float* bv  = (const float*)d_in[7];
    const float* Wo  = (const float*)d_in[8];
    const float* bo  = (const float*)d_in[9];
    const float* lnw = (const float*)d_in[10];
    const float* lnb = (const float*)d_in[11];

    float* out   = (float*)d_out;
    float* probs = out + (size_t)BS * HID;

    const int GEMM_N128_SMEM = 4 * 256 * 20 * 4;  // 81920
    const int GEMM_N64_SMEM  = 4 * 192 * 20 * 4;  // 61440
    const int POSATT_SMEM = 2 * 128 * 72 * 2;     // 36864
    const int FUSED_SMEM = (32 * 72 + 6 * 64 * 72) * 2 + 512 * 4;  // 61952

    cudaFuncSetAttribute(k_proj,     cudaFuncAttributeMaxDynamicSharedMemorySize, GEMM_N128_SMEM);
    cudaFuncSetAttribute(k_posatt16, cudaFuncAttributeMaxDynamicSharedMemorySize, POSATT_SMEM);
    cudaFuncSetAttribute(k_out,      cudaFuncAttributeMaxDynamicSharedMemorySize, GEMM_N128_SMEM);
    cudaFuncSetAttribute(k_ctx,      cudaFuncAttributeMaxDynamicSharedMemorySize, GEMM_N64_SMEM);
    cudaFuncSetAttribute(k_fused_scores, cudaFuncAttributeMaxDynamicSharedMemorySize, FUSED_SMEM);

    relb_kernel<<<8, 256>>>();
    k_proj<<<dim3(HID / 128, 104), 256, GEMM_N128_SMEM>>>(hs, rel, Wq, bq, Wk, bk, Wv, bv);
    k_posatt16<<<3072, 256, POSATT_SMEM>>>();
    k_fused_scores<<<dim3(SEQ / 32, BAT * NH), 512, FUSED_SMEM>>>(probs);
    k_ctx<<<dim3(SEQ / 128, BAT * NH), 256, GEMM_N64_SMEM>>>(probs);
    k_out<<<dim3(HID / 128, BS / 128), 256, GEMM_N128_SMEM>>>(hs, Wo, bo);
    ln_kernel<<<BS, 256>>>(lnw, lnb, out);
}

// round 16
// speedup vs baseline: 1.3107x; 1.1443x over previous
#include <cuda_runtime.h>
#include <cuda_fp16.h>
#include <math.h>

#define NH   12
#define D    64
#define SEQ  1024
#define BAT  4
#define HID  768
#define BS   4096      // BAT*SEQ
#define POS  512       // 2*span
#define SPAN 256

// -------- scratch (static device memory; no allocations) --------
__device__ __half g_hs16[BS * HID];
__device__ __half g_rel16[POS * HID];
__device__ __half g_wq16[HID * HID];
__device__ __half g_wk16[HID * HID];
__device__ __half g_wv16[HID * HID];
__device__ __half g_wo16[HID * HID];
__device__ __half g_q[BS * HID];                   // fp16
__device__ __half g_k[BS * HID];                   // fp16
__device__ __half g_v16[BS * HID];                 // fp16, [b][h][d][s]
__device__ __half g_ctx16[BS * HID];               // fp16
__device__ __half g_probs16[(size_t)BAT * NH * SEQ * SEQ];  // fp16 probs copy
__device__ float  g_pre[BS * HID];
__device__ __half g_posk[POS * HID];               // fp16
__device__ __half g_posq[POS * HID];               // fp16
__device__ __half g_c2p[(size_t)NH * BS * POS];    // [h][b*S+s][512] fp16
__device__ __half g_p2cT[(size_t)NH * POS * BS];   // [h][bucket][b*S+t] fp16
__device__ int    g_c2pidx[2048];

// -------- relative-position bucket table (matches numpy exactly) --------
__global__ void relb_kernel() {
    int i = blockIdx.x * blockDim.x + threadIdx.x;
    if (i >= 2047) return;
    int rel = i - 1023;
    const int mid = 128;
    int sgn = (rel > 0) - (rel < 0);
    float abs_pos = (rel < mid && rel > -mid) ? (float)(mid - 1) : (float)abs(rel);
    float num32 = logf(abs_pos / 128.0f);
    double log_pos = ceil((double)num32 / log(511.0 / 128.0) * 127.0) + 128.0;
    long long bucket = (abs_pos <= 128.0f) ? (long long)rel
                                           : (long long)(log_pos * (double)sgn);
    int bi = (int)bucket;
    int c = bi + SPAN;  c = c < 0 ? 0 : (c > 2 * SPAN - 1 ? 2 * SPAN - 1 : c);
    g_c2pidx[i] = c;
}

// -------- prep: fp32 -> fp16 conversions --------
__global__ void k_prep(const float* __restrict__ hs, const float* __restrict__ rel,
                       const float* __restrict__ Wq, const float* __restrict__ Wk,
                       const float* __restrict__ Wv, const float* __restrict__ Wo) {
    long long i = (long long)blockIdx.x * 256 + threadIdx.x;
    int z = blockIdx.y;
    const float* src;
    __half* dst;
    long long n;
    switch (z) {
        case 0: src = hs;  dst = g_hs16;  n = (long long)BS * HID; break;
        case 1: src = rel; dst = g_rel16; n = (long long)POS * HID; break;
        case 2: src = Wq;  dst = g_wq16;  n = HID * HID; break;
        case 3: src = Wk;  dst = g_wk16;  n = HID * HID; break;
        case 4: src = Wv;  dst = g_wv16;  n = HID * HID; break;
        default: src = Wo; dst = g_wo16;  n = HID * HID; break;
    }
    if (i < n) dst[i] = __float2half_rn(src[i]);
}

// -------- mma / cp helpers --------
__device__ __forceinline__ void mma_fp16(float* c, const unsigned* a, unsigned b0, unsigned b1) {
    asm volatile(
        "mma.sync.aligned.m16n8k16.row.col.f32.f16.f16.f32 "
        "{%0,%1,%2,%3},{%4,%5,%6,%7},{%8,%9},{%0,%1,%2,%3};"
        : "+f"(c[0]), "+f"(c[1]), "+f"(c[2]), "+f"(c[3])
        : "r"(a[0]), "r"(a[1]), "r"(a[2]), "r"(a[3]), "r"(b0), "r"(b1));
}

__device__ __forceinline__ void cp_async16(unsigned dst, const void* src) {
    asm volatile("cp.async.cg.shared.global [%0], [%1], 16;\n" :: "r"(dst), "l"(src));
}

// ======== generic fp16 NT GEMM with 4-stage cp.async ring ========
// C[TM x TN] tile; TM=128, TN 64/128. 256 threads. BK=32 (2 k16 MMA steps/chunk).
// EPI: 0 plain half, 1 +bias half, 2 +bias+resid -> float, 3 +bias scatter vT half
template<int EPI, int TM, int TN, typename OutT>
__device__ __forceinline__ void gemm16_body(
    const __half* __restrict__ A, int lda,
    const __half* __restrict__ B, int ldb,
    const float* __restrict__ bias,
    const float* __restrict__ resid, int ldr,
    OutT* __restrict__ C, long long ldc, int K,
    int row0, int col0)
{
    constexpr int MI = 2;
    constexpr int NI = (TN == 64) ? 4 : 8;
    constexpr int ROWS = TM + TN;
    constexpr int CP = ROWS / 64;          // granules/thread/stage
    extern __shared__ __half S16[];        // [4][ROWS][40]
    int tid = threadIdx.x;
    int wid = tid >> 5, lane = tid & 31;
    int quad = lane >> 2, qt = lane & 3;
    int wm, wn;
    if (TN == 64) { wm = (wid >> 1) * 32; wn = (wid & 1) * 32; }
    else          { wm = (wid & 3) * 32;  wn = (wid >> 2) * 64; }

    const __half* gsrc[CP];
    unsigned soff[CP];
    unsigned sbase = (unsigned)__cvta_generic_to_shared(S16);
#pragma unroll
    for (int j = 0; j < CP; j++) {
        int lin = tid + j * 256;
        int row = lin >> 2, g = lin & 3;   // 4 x 16B granules per 32-half row
        soff[j] = row * 40 + g * 8;
        gsrc[j] = (row < TM) ? A + (long long)(row0 + row) * lda + g * 8
                             : B + (long long)(col0 + row - TM) * ldb + g * 8;
    }
    auto issue = [&](int cc) {
        int slot = cc & 3;
        long long k0 = (long long)cc * 32;
#pragma unroll
        for (int j = 0; j < CP; j++)
            cp_async16(sbase + (slot * ROWS * 40 + soff[j]) * 2, gsrc[j] + k0);
        asm volatile("cp.async.commit_group;\n");
    };

    float acc[MI][NI][4];
#pragma unroll
    for (int i = 0; i < MI; i++)
#pragma unroll
        for (int j = 0; j < NI; j++)
#pragma unroll
            for (int l = 0; l < 4; l++) acc[i][j][l] = 0.0f;

    auto comp = [&](int slot) {
        const __half* Sb = S16 + slot * ROWS * 40;
#pragma unroll
        for (int ks = 0; ks < 2; ks++) {
            int k0 = ks * 16;
            unsigned af[MI][4];
#pragma unroll
            for (int mi = 0; mi < MI; mi++) {
                int r = wm + mi * 16 + quad;
                af[mi][0] = *reinterpret_cast<const unsigned*>(Sb + r * 40 + k0 + 2 * qt);
                af[mi][1] = *reinterpret_cast<const unsigned*>(Sb + (r + 8) * 40 + k0 + 2 * qt);
                af[mi][2] = *reinterpret_cast<const unsigned*>(Sb + r * 40 + k0 + 2 * qt + 8);
                af[mi][3] = *reinterpret_cast<const unsigned*>(Sb + (r + 8) * 40 + k0 + 2 * qt + 8);
            }
#pragma unroll
            for (int ni = 0; ni < NI; ni++) {
                const __half* bp = Sb + (TM + wn + ni * 8 + quad) * 40 + k0 + 2 * qt;
                unsigned b0 = *reinterpret_cast<const unsigned*>(bp);
                unsigned b1 = *reinterpret_cast<const unsigned*>(bp + 8);
#pragma unroll
                for (int mi = 0; mi < MI; mi++)
                    mma_fp16(acc[mi][ni], af[mi], b0, b1);
            }
        }
    };

    int nst = K >> 5;
    issue(0); issue(1); issue(2);
    for (int c = 0; c < nst; c++) {
        asm volatile("cp.async.wait_group %0;\n" :: "n"(2));
        __syncthreads();
        if (c + 3 < nst) issue(c + 3);
        else asm volatile("cp.async.commit_group;\n");
        comp(c & 3);
    }

    // epilogue
#pragma unroll
    for (int mi = 0; mi < MI; mi++) {
#pragma unroll
        for (int half = 0; half < 2; half++) {
            long long row = row0 + wm + mi * 16 + quad + half * 8;
#pragma unroll
            for (int ni = 0; ni < NI; ni++) {
                long long col = col0 + wn + ni * 8 + qt * 2;
                float v0 = acc[mi][ni][half * 2 + 0];
                float v1 = acc[mi][ni][half * 2 + 1];
                if (EPI >= 1) { v0 += bias[col]; v1 += bias[col + 1]; }
                if (EPI == 2) {
                    v0 += resid[row * ldr + col];
                    v1 += resid[row * ldr + col + 1];
                    *reinterpret_cast<float2*>((float*)C + row * ldc + col) =
                        make_float2(v0, v1);
                } else if (EPI == 3) {
                    int bb = (int)(row >> 10), ss = (int)(row & 1023);
                    int hh = (int)(col >> 6), dd = (int)(col & 63);
                    ((__half*)C)[((((long long)bb * NH + hh) * D + dd) << 10) + ss] = __float2half_rn(v0);
                    hh = (int)((col + 1) >> 6); dd = (int)((col + 1) & 63);
                    ((__half*)C)[((((long long)bb * NH + hh) * D + dd) << 10) + ss] = __float2half_rn(v1);
                } else {
                    *reinterpret_cast<__half2*>((__half*)C + row * ldc + col) =
                        __floats2half2_rn(v0, v1);
                }
            }
        }
    }
}

// -------- merged projection kernel (all fp16) --------
__global__ void __launch_bounds__(256, 2) k_proj(
    const float* __restrict__ bq, const float* __restrict__ bk, const float* __restrict__ bv)
{
    int y = blockIdx.y;
    int col0 = blockIdx.x * 128;
    if (y < 32)
        gemm16_body<1, 128, 128>(g_hs16, HID, g_wq16, HID, bq, nullptr, 0, g_q, HID, HID, y * 128, col0);
    else if (y < 64)
        gemm16_body<1, 128, 128>(g_hs16, HID, g_wk16, HID, bk, nullptr, 0, g_k, HID, HID, (y - 32) * 128, col0);
    else if (y < 96)
        gemm16_body<3, 128, 128>(g_hs16, HID, g_wv16, HID, bv, nullptr, 0, g_v16, HID, HID, (y - 64) * 128, col0);
    else if (y < 100)
        gemm16_body<1, 128, 128>(g_rel16, HID, g_wk16, HID, bk, nullptr, 0, g_posk, HID, HID, (y - 96) * 128, col0);
    else
        gemm16_body<1, 128, 128>(g_rel16, HID, g_wq16, HID, bq, nullptr, 0, g_posq, HID, HID, (y - 100) * 128, col0);
}

// -------- pos-att (fp16, K=64) --------
__global__ void __launch_bounds__(256, 2) k_posatt() {
    int z = blockIdx.x;
    if (z < 1536) {
        int h = z >> 7, r = z & 127;
        gemm16_body<0, 128, 128>(g_q + h * D, HID, g_posk + h * D, HID, nullptr, nullptr, 0,
                                 g_c2p + (size_t)h * BS * POS, POS, D,
                                 (r >> 2) * 128, (r & 3) * 128);
    } else {
        z -= 1536;
        int h = z >> 7, r = z & 127;
        gemm16_body<0, 128, 128>(g_posq + h * D, HID, g_k + h * D, HID, nullptr, nullptr, 0,
                                 g_p2cT + (size_t)h * POS * BS, BS, D,
                                 (r >> 5) * 128, (r & 31) * 128);
    }
}

// ======== FUSED fp16 scores + in-loop gathers + softmax -> probs (fp32 + fp16) ========
__global__ void __launch_bounds__(512, 1) k_fused_scores(float* __restrict__ probs) {
    extern __shared__ char dynb[];
    __half* Qs = (__half*)dynb;                      // [32][72]
    __half* Ks = Qs + 32 * 72;                       // [6][64][72] ring
    float* red_m = (float*)(Ks + 6 * 64 * 72);       // [32][8]
    float* red_s = red_m + 256;                      // [32][8]

    int s0 = blockIdx.x * 32;
    int bh = blockIdx.y;
    int b = bh / NH, h = bh % NH;
    int tid = threadIdx.x;
    int w = tid >> 5, lane = tid & 31;
    int quad = lane >> 2, qt = lane & 3;
    int wm = (w >> 3) * 16;
    int wn = (w & 7) * 8;
    int nw = w & 7;

    const __half* kptr = g_k + ((long long)b * SEQ) * HID + h * D;
    unsigned ks_base = (unsigned)__cvta_generic_to_shared(Ks);

    int r0 = tid >> 3, g0 = tid & 7;

    auto issue_k = [&](int cc) {
        int slot = cc % 6;
        cp_async16(ks_base + (unsigned)((slot * 64 + r0) * 72 + g0 * 8) * 2,
                   kptr + (long long)(cc * 64 + r0) * HID + g0 * 8);
        asm volatile("cp.async.commit_group;\n");
    };

    issue_k(0); issue_k(1); issue_k(2); issue_k(3);

    {
        int m = tid >> 4, c = (tid & 15) * 4;
        *reinterpret_cast<uint2*>(Qs + m * 72 + c) =
            *reinterpret_cast<const uint2*>(
                g_q + ((long long)(b * SEQ + s0 + m)) * HID + h * D + c);
    }
    __syncthreads();

    unsigned areg[4][4];
#pragma unroll
    for (int ks = 0; ks < 4; ks++) {
        int k0 = ks * 16;
        areg[ks][0] = *reinterpret_cast<const unsigned*>(Qs + (wm + quad) * 72 + k0 + 2 * qt);
        areg[ks][1] = *reinterpret_cast<const unsigned*>(Qs + (wm + quad + 8) * 72 + k0 + 2 * qt);
        areg[ks][2] = *reinterpret_cast<const unsigned*>(Qs + (wm + quad) * 72 + k0 + 2 * qt + 8);
        areg[ks][3] = *reinterpret_cast<const unsigned*>(Qs + (wm + quad + 8) * 72 + k0 + 2 * qt + 8);
    }

    float acc[16][4];
#pragma unroll
    for (int f = 0; f < 16; f++)
#pragma unroll
        for (int j = 0; j < 4; j++) acc[f][j] = 0.0f;

    const float inv = rsqrtf(192.0f);
    int sl0 = wm + quad;
    long long c2pb0 = ((long long)h * BS + b * SEQ + s0 + sl0) * POS;
    long long c2pb1 = c2pb0 + 8LL * POS;
    long long pTb = (long long)h * POS * BS + (long long)b * SEQ;
    float rmax[2] = {-1e30f, -1e30f};

    auto do_chunk = [&](int c) {
        int slot = c % 6;
        const __half* kb = Ks + (slot * 64 + wn + quad) * 72;
#pragma unroll
        for (int ks = 0; ks < 4; ks++) {
            int k0 = ks * 16;
            unsigned b0 = *reinterpret_cast<const unsigned*>(kb + k0 + 2 * qt);
            unsigned b1 = *reinterpret_cast<const unsigned*>(kb + k0 + 2 * qt + 8);
            mma_fp16(acc[c], areg[ks], b0, b1);
        }
        int colb = c * 64 + wn + qt * 2;
#pragma unroll
        for (int rh = 0; rh < 2; rh++) {
            int s = s0 + sl0 + rh * 8;
            long long cb = rh ? c2pb1 : c2pb0;
#pragma unroll
            for (int e = 0; e < 2; e++) {
                int t = colb + e;
                int ci = __ldg(&g_c2pidx[s - t + 1023]);
                float x = acc[c][rh * 2 + e]
                        + __half2float(__ldg(&g_c2p[cb + ci]))
                        + __half2float(__ldg(&g_p2cT[pTb + (long long)ci * BS + t]));
                x *= inv;
                acc[c][rh * 2 + e] = x;
                rmax[rh] = fmaxf(rmax[rh], x);
            }
        }
    };

#pragma unroll
    for (int c = 0; c < 16; c += 2) {
        asm volatile("cp.async.wait_group %0;\n" :: "n"(2));
        __syncthreads();
        if (c + 4 < 16) issue_k(c + 4);
        else            asm volatile("cp.async.commit_group;\n");
        if (c + 5 < 16) issue_k(c + 5);
        else            asm volatile("cp.async.commit_group;\n");
        do_chunk(c);
        do_chunk(c + 1);
    }

#pragma unroll
    for (int o = 1; o <= 2; o <<= 1) {
        rmax[0] = fmaxf(rmax[0], __shfl_xor_sync(0xffffffffu, rmax[0], o));
        rmax[1] = fmaxf(rmax[1], __shfl_xor_sync(0xffffffffu, rmax[1], o));
    }
    if (qt == 0) { red_m[sl0 * 8 + nw] = rmax[0]; red_m[(sl0 + 8) * 8 + nw] = rmax[1]; }
    __syncthreads();
    float mrow[2];
#pragma unroll
    for (int rh = 0; rh < 2; rh++) {
        float m = red_m[(sl0 + rh * 8) * 8];
#pragma unroll
        for (int j = 1; j < 8; j++) m = fmaxf(m, red_m[(sl0 + rh * 8) * 8 + j]);
        mrow[rh] = m;
    }
    float rsum[2] = {0.0f, 0.0f};
#pragma unroll
    for (int f = 0; f < 16; f++)
#pragma unroll
        for (int rh = 0; rh < 2; rh++)
#pragma unroll
            for (int e = 0; e < 2; e++) {
                float v = __expf(acc[f][rh * 2 + e] - mrow[rh]);
                acc[f][rh * 2 + e] = v;
                rsum[rh] += v;
            }
#pragma unroll
    for (int o = 1; o <= 2; o <<= 1) {
        rsum[0] += __shfl_xor_sync(0xffffffffu, rsum[0], o);
        rsum[1] += __shfl_xor_sync(0xffffffffu, rsum[1], o);
    }
    if (qt == 0) { red_s[sl0 * 8 + nw] = rsum[0]; red_s[(sl0 + 8) * 8 + nw] = rsum[1]; }
    __syncthreads();
    float rinv[2];
#pragma unroll
    for (int rh = 0; rh < 2; rh++) {
        float sum = 0.0f;
#pragma unroll
        for (int j = 0; j < 8; j++) sum += red_s[(sl0 + rh * 8) * 8 + j];
        rinv[rh] = 1.0f / sum;
    }
#pragma unroll
    for (int rh = 0; rh < 2; rh++) {
        long long rowoff = ((long long)bh * SEQ + s0 + sl0 + rh * 8) * SEQ;
        float* prow = probs + rowoff;
        __half* prow16 = g_probs16 + rowoff;
#pragma unroll
        for (int f = 0; f < 16; f++) {
            int colb = f * 64 + wn + qt * 2;
            float p0 = acc[f][rh * 2] * rinv[rh];
            float p1 = acc[f][rh * 2 + 1] * rinv[rh];
            *reinterpret_cast<float2*>(&prow[colb]) = make_float2(p0, p1);
            *reinterpret_cast<__half2*>(&prow16[colb]) = __floats2half2_rn(p0, p1);
        }
    }
}

// ctx16 = probs16 @ v16^T  (fp16, K=1024)
__global__ void __launch_bounds__(256, 2) k_ctx() {
    int z = blockIdx.y;
    int b = z / NH, h = z % NH;
    gemm16_body<0, 128, 64>(g_probs16 + (size_t)z * SEQ * SEQ, SEQ,
                            g_v16 + (size_t)z * D * SEQ, SEQ,
                            nullptr, nullptr, 0,
                            g_ctx16 + (size_t)(b * SEQ) * HID + h * D, HID, SEQ,
                            blockIdx.x * 128, 0);
}

// out-proj: fp16 MMA, fp32 bias+resid, fp32 output
__global__ void __launch_bounds__(256, 2) k_out(const float* __restrict__ hs,
                                                const float* __restrict__ bo) {
    gemm16_body<2, 128, 128>(g_ctx16, HID, g_wo16, HID, bo, hs, HID, g_pre, HID, HID,
                             blockIdx.y * 128, blockIdx.x * 128);
}

// -------- layernorm over rows of g_pre --------
__global__ void ln_kernel(const float* __restrict__ lnw, const float* __restrict__ lnb,
                          float* __restrict__ out) {
    int row = blockIdx.x;
    const float* x = g_pre + (long long)row * HID;
    float* o = out + (long long)row * HID;
    int tid = threadIdx.x;
    __shared__ float red[8];
    float v[3];
    float s = 0.0f;
#pragma unroll
    for (int k = 0; k < 3; k++) {
        v[k] = x[tid + k * 256];
        s += v[k];
    }
#pragma unroll
    for (int o2 = 16; o2; o2 >>= 1) s += __shfl_xor_sync(0xffffffffu, s, o2);
    if ((tid & 31) == 0) red[tid >> 5] = s;
    __syncthreads();
    if (tid == 0) {
        float x2 = 0.0f;
#pragma unroll
        for (int i = 0; i < 8; i++) x2 += red[i];
        red[0] = x2;
    }
    __syncthreads();
    float mu = red[0] / (float)HID;
    __syncthreads();
    float sq = 0.0f;
#pragma unroll
    for (int k = 0; k < 3; k++) {
        float d = v[k] - mu;
        sq += d * d;
    }
#pragma unroll
    for (int o2 = 16; o2; o2 >>= 1) sq += __shfl_xor_sync(0xffffffffu, sq, o2);
    if ((tid & 31) == 0) red[tid >> 5] = sq;
    __syncthreads();
    if (tid == 0) {
        float x2 = 0.0f;
#pragma unroll
        for (int i = 0; i < 8; i++) x2 += red[i];
        red[0] = x2;
    }
    __syncthreads();
    float var = red[0] / (float)HID;
    float rstd = 1.0f / sqrtf(var + 1e-7f);
#pragma unroll
    for (int k = 0; k < 3; k++) {
        int c = tid + k * 256;
        o[c] = lnw[c] * (v[k] - mu) * rstd + lnb[c];
    }
}

extern "C" void kernel_launch(void* const* d_in, const int* in_sizes, int n_in,
                              void* d_out, int out_size) {
    const float* hs  = (const float*)d_in[0];
    const float* rel = (const float*)d_in[1];
    const float* Wq  = (const float*)d_in[2];
    const float* bq  = (const float*)d_in[3];
    const float* Wk  = (const float*)d_in[4];
    const float* bk  = (const float*)d_in[5];
    const float* Wv  = (const float*)d_in[6];
    const float* bv  = (const float*)d_in[7];
    const float* Wo  = (const float*)d_in[8];
    const float* bo  = (const float*)d_in[9];
    const float* lnw = (const float*)d_in[10];
    const float* lnb = (const float*)d_in[11];

    float* out   = (float*)d_out;
    float* probs = out + (size_t)BS * HID;

    const int G16_N128_SMEM = 4 * 256 * 40 * 2;  // 81920
    const int G16_N64_SMEM  = 4 * 192 * 40 * 2;  // 61440
    const int FUSED_SMEM = (32 * 72 + 6 * 64 * 72) * 2 + 512 * 4;  // 61952

    cudaFuncSetAttribute(k_proj,   cudaFuncAttributeMaxDynamicSharedMemorySize, G16_N128_SMEM);
    cudaFuncSetAttribute(k_posatt, cudaFuncAttributeMaxDynamicSharedMemorySize, G16_N128_SMEM);
    cudaFuncSetAttribute(k_out,    cudaFuncAttributeMaxDynamicSharedMemorySize, G16_N128_SMEM);
    cudaFuncSetAttribute(k_ctx,    cudaFuncAttributeMaxDynamicSharedMemorySize, G16_N64_SMEM);
    cudaFuncSetAttribute(k_fused_scores, cudaFuncAttributeMaxDynamicSharedMemorySize, FUSED_SMEM);

    relb_kernel<<<8, 256>>>();
    k_prep<<<dim3((BS * HID + 255) / 256, 6), 256>>>(hs, rel, Wq, Wk, Wv, Wo);
    k_proj<<<dim3(HID / 128, 104), 256, G16_N128_SMEM>>>(bq, bk, bv);
    k_posatt<<<3072, 256, G16_N128_SMEM>>>();
    k_fused_scores<<<dim3(SEQ / 32, BAT * NH), 512, FUSED_SMEM>>>(probs);
    k_ctx<<<dim3(SEQ / 128, BAT * NH), 256, G16_N64_SMEM>>>();
    k_out<<<dim3(HID / 128, BS / 128), 256, G16_N128_SMEM>>>(hs, bo);
    ln_kernel<<<BS, 256>>>(lnw, lnb, out);
}

// round 17
// speedup vs baseline: 1.3176x; 1.0052x over previous
#include <cuda_runtime.h>
#include <cuda_fp16.h>
#include <math.h>

#define NH   12
#define D    64
#define SEQ  1024
#define BAT  4
#define HID  768
#define BS   4096      // BAT*SEQ
#define POS  512       // 2*span
#define SPAN 256

// -------- scratch (static device memory; no allocations) --------
__device__ __half g_hs16[BS * HID];
__device__ __half g_rel16[POS * HID];
__device__ __half g_wq16[HID * HID];
__device__ __half g_wk16[HID * HID];
__device__ __half g_wv16[HID * HID];
__device__ __half g_wo16[HID * HID];
__device__ __half g_q[BS * HID];                   // fp16
__device__ __half g_k[BS * HID];                   // fp16
__device__ __half g_v16[BS * HID];                 // fp16, [b][h][d][s]
__device__ __half g_ctx16[BS * HID];               // fp16
__device__ __half g_probs16[(size_t)BAT * NH * SEQ * SEQ];  // fp16 probs copy
__device__ float  g_pre[BS * HID];
__device__ __half g_posk[POS * HID];               // fp16
__device__ __half g_posq[POS * HID];               // fp16
__device__ __half g_c2p[(size_t)NH * BS * POS];    // [h][b*S+s][512] fp16
__device__ __half g_p2cT[(size_t)NH * POS * BS];   // [h][bucket][b*S+t] fp16
__device__ int    g_c2pidx[2048];

// -------- relative-position bucket table (matches numpy exactly) --------
__global__ void relb_kernel() {
    int i = blockIdx.x * blockDim.x + threadIdx.x;
    if (i >= 2047) return;
    int rel = i - 1023;
    const int mid = 128;
    int sgn = (rel > 0) - (rel < 0);
    float abs_pos = (rel < mid && rel > -mid) ? (float)(mid - 1) : (float)abs(rel);
    float num32 = logf(abs_pos / 128.0f);
    double log_pos = ceil((double)num32 / log(511.0 / 128.0) * 127.0) + 128.0;
    long long bucket = (abs_pos <= 128.0f) ? (long long)rel
                                           : (long long)(log_pos * (double)sgn);
    int bi = (int)bucket;
    int c = bi + SPAN;  c = c < 0 ? 0 : (c > 2 * SPAN - 1 ? 2 * SPAN - 1 : c);
    g_c2pidx[i] = c;
}

// -------- prep: fp32 -> fp16 conversions --------
__global__ void k_prep(const float* __restrict__ hs, const float* __restrict__ rel,
                       const float* __restrict__ Wq, const float* __restrict__ Wk,
                       const float* __restrict__ Wv, const float* __restrict__ Wo) {
    long long i = (long long)blockIdx.x * 256 + threadIdx.x;
    int z = blockIdx.y;
    const float* src;
    __half* dst;
    long long n;
    switch (z) {
        case 0: src = hs;  dst = g_hs16;  n = (long long)BS * HID; break;
        case 1: src = rel; dst = g_rel16; n = (long long)POS * HID; break;
        case 2: src = Wq;  dst = g_wq16;  n = HID * HID; break;
        case 3: src = Wk;  dst = g_wk16;  n = HID * HID; break;
        case 4: src = Wv;  dst = g_wv16;  n = HID * HID; break;
        default: src = Wo; dst = g_wo16;  n = HID * HID; break;
    }
    if (i < n) dst[i] = __float2half_rn(src[i]);
}

// -------- mma / cp helpers --------
__device__ __forceinline__ void mma_fp16(float* c, const unsigned* a, unsigned b0, unsigned b1) {
    asm volatile(
        "mma.sync.aligned.m16n8k16.row.col.f32.f16.f16.f32 "
        "{%0,%1,%2,%3},{%4,%5,%6,%7},{%8,%9},{%0,%1,%2,%3};"
        : "+f"(c[0]), "+f"(c[1]), "+f"(c[2]), "+f"(c[3])
        : "r"(a[0]), "r"(a[1]), "r"(a[2]), "r"(a[3]), "r"(b0), "r"(b1));
}

__device__ __forceinline__ void cp_async16(unsigned dst, const void* src) {
    asm volatile("cp.async.cg.shared.global [%0], [%1], 16;\n" :: "r"(dst), "l"(src));
}

// ======== generic fp16 NT GEMM with 4-stage cp.async ring ========
// C[TM x TN] tile; TM=128, TN 64/128. 256 threads. BK=32 (2 k16 MMA steps/chunk).
// EPI: 0 plain half, 1 +bias half, 2 +bias+resid -> float, 3 +bias scatter vT half
template<int EPI, int TM, int TN, typename OutT>
__device__ __forceinline__ void gemm16_body(
    const __half* __restrict__ A, int lda,
    const __half* __restrict__ B, int ldb,
    const float* __restrict__ bias,
    const float* __restrict__ resid, int ldr,
    OutT* __restrict__ C, long long ldc, int K,
    int row0, int col0)
{
    constexpr int MI = 2;
    constexpr int NI = (TN == 64) ? 4 : 8;
    constexpr int ROWS = TM + TN;
    constexpr int CP = ROWS / 64;
    extern __shared__ __half S16[];        // [4][ROWS][40]
    int tid = threadIdx.x;
    int wid = tid >> 5, lane = tid & 31;
    int quad = lane >> 2, qt = lane & 3;
    int wm, wn;
    if (TN == 64) { wm = (wid >> 1) * 32; wn = (wid & 1) * 32; }
    else          { wm = (wid & 3) * 32;  wn = (wid >> 2) * 64; }

    const __half* gsrc[CP];
    unsigned soff[CP];
    unsigned sbase = (unsigned)__cvta_generic_to_shared(S16);
#pragma unroll
    for (int j = 0; j < CP; j++) {
        int lin = tid + j * 256;
        int row = lin >> 2, g = lin & 3;
        soff[j] = row * 40 + g * 8;
        gsrc[j] = (row < TM) ? A + (long long)(row0 + row) * lda + g * 8
                             : B + (long long)(col0 + row - TM) * ldb + g * 8;
    }
    auto issue = [&](int cc) {
        int slot = cc & 3;
        long long k0 = (long long)cc * 32;
#pragma unroll
        for (int j = 0; j < CP; j++)
            cp_async16(sbase + (slot * ROWS * 40 + soff[j]) * 2, gsrc[j] + k0);
        asm volatile("cp.async.commit_group;\n");
    };

    float acc[MI][NI][4];
#pragma unroll
    for (int i = 0; i < MI; i++)
#pragma unroll
        for (int j = 0; j < NI; j++)
#pragma unroll
            for (int l = 0; l < 4; l++) acc[i][j][l] = 0.0f;

    auto comp = [&](int slot) {
        const __half* Sb = S16 + slot * ROWS * 40;
#pragma unroll
        for (int ks = 0; ks < 2; ks++) {
            int k0 = ks * 16;
            unsigned af[MI][4];
#pragma unroll
            for (int mi = 0; mi < MI; mi++) {
                int r = wm + mi * 16 + quad;
                af[mi][0] = *reinterpret_cast<const unsigned*>(Sb + r * 40 + k0 + 2 * qt);
                af[mi][1] = *reinterpret_cast<const unsigned*>(Sb + (r + 8) * 40 + k0 + 2 * qt);
                af[mi][2] = *reinterpret_cast<const unsigned*>(Sb + r * 40 + k0 + 2 * qt + 8);
                af[mi][3] = *reinterpret_cast<const unsigned*>(Sb + (r + 8) * 40 + k0 + 2 * qt + 8);
            }
#pragma unroll
            for (int ni = 0; ni < NI; ni++) {
                const __half* bp = Sb + (TM + wn + ni * 8 + quad) * 40 + k0 + 2 * qt;
                unsigned b0 = *reinterpret_cast<const unsigned*>(bp);
                unsigned b1 = *reinterpret_cast<const unsigned*>(bp + 8);
#pragma unroll
                for (int mi = 0; mi < MI; mi++)
                    mma_fp16(acc[mi][ni], af[mi], b0, b1);
            }
        }
    };

    int nst = K >> 5;
    issue(0);
    if (nst > 1) issue(1); else asm volatile("cp.async.commit_group;\n");
    if (nst > 2) issue(2); else asm volatile("cp.async.commit_group;\n");
    for (int c = 0; c < nst; c++) {
        asm volatile("cp.async.wait_group %0;\n" :: "n"(2));
        __syncthreads();
        if (c + 3 < nst) issue(c + 3);
        else asm volatile("cp.async.commit_group;\n");
        comp(c & 3);
    }

    // epilogue
#pragma unroll
    for (int mi = 0; mi < MI; mi++) {
#pragma unroll
        for (int half = 0; half < 2; half++) {
            long long row = row0 + wm + mi * 16 + quad + half * 8;
#pragma unroll
            for (int ni = 0; ni < NI; ni++) {
                long long col = col0 + wn + ni * 8 + qt * 2;
                float v0 = acc[mi][ni][half * 2 + 0];
                float v1 = acc[mi][ni][half * 2 + 1];
                if (EPI >= 1) { v0 += bias[col]; v1 += bias[col + 1]; }
                if (EPI == 2) {
                    v0 += resid[row * ldr + col];
                    v1 += resid[row * ldr + col + 1];
                    *reinterpret_cast<float2*>((float*)C + row * ldc + col) =
                        make_float2(v0, v1);
                } else if (EPI == 3) {
                    int bb = (int)(row >> 10), ss = (int)(row & 1023);
                    int hh = (int)(col >> 6), dd = (int)(col & 63);
                    ((__half*)C)[((((long long)bb * NH + hh) * D + dd) << 10) + ss] = __float2half_rn(v0);
                    hh = (int)((col + 1) >> 6); dd = (int)((col + 1) & 63);
                    ((__half*)C)[((((long long)bb * NH + hh) * D + dd) << 10) + ss] = __float2half_rn(v1);
                } else {
                    *reinterpret_cast<__half2*>((__half*)C + row * ldc + col) =
                        __floats2half2_rn(v0, v1);
                }
            }
        }
    }
}

// -------- merged projection kernel (all fp16) --------
__global__ void __launch_bounds__(256, 2) k_proj(
    const float* __restrict__ bq, const float* __restrict__ bk, const float* __restrict__ bv)
{
    int y = blockIdx.y;
    int col0 = blockIdx.x * 128;
    if (y < 32)
        gemm16_body<1, 128, 128>(g_hs16, HID, g_wq16, HID, bq, nullptr, 0, g_q, HID, HID, y * 128, col0);
    else if (y < 64)
        gemm16_body<1, 128, 128>(g_hs16, HID, g_wk16, HID, bk, nullptr, 0, g_k, HID, HID, (y - 32) * 128, col0);
    else if (y < 96)
        gemm16_body<3, 128, 128>(g_hs16, HID, g_wv16, HID, bv, nullptr, 0, g_v16, HID, HID, (y - 64) * 128, col0);
    else if (y < 100)
        gemm16_body<1, 128, 128>(g_rel16, HID, g_wk16, HID, bk, nullptr, 0, g_posk, HID, HID, (y - 96) * 128, col0);
    else
        gemm16_body<1, 128, 128>(g_rel16, HID, g_wq16, HID, bq, nullptr, 0, g_posq, HID, HID, (y - 100) * 128, col0);
}

// -------- pos-att (fp16, K=64) --------
__global__ void __launch_bounds__(256, 2) k_posatt() {
    int z = blockIdx.x;
    if (z < 1536) {
        int h = z >> 7, r = z & 127;
        gemm16_body<0, 128, 128>(g_q + h * D, HID, g_posk + h * D, HID, nullptr, nullptr, 0,
                                 g_c2p + (size_t)h * BS * POS, POS, D,
                                 (r >> 2) * 128, (r & 3) * 128);
    } else {
        z -= 1536;
        int h = z >> 7, r = z & 127;
        gemm16_body<0, 128, 128>(g_posq + h * D, HID, g_k + h * D, HID, nullptr, nullptr, 0,
                                 g_p2cT + (size_t)h * POS * BS, BS, D,
                                 (r >> 5) * 128, (r & 31) * 128);
    }
}

// ======== FUSED fp16 scores + pipelined gathers + softmax -> probs ========
// 512 threads = 16 warps (2 m x 8 n). CTA tile: 32 rows x 1024 cols.
// Index window staged in smem (kills the idx->data dependent L2 chain);
// per chunk: gather LDGs issued BEFORE the MMA block so L2 latency overlaps MMA.
__global__ void __launch_bounds__(512, 1) k_fused_scores(float* __restrict__ probs) {
    extern __shared__ char dynb[];
    __half* Qs = (__half*)dynb;                      // [32][72]
    __half* Ks = Qs + 32 * 72;                       // [6][64][72] ring
    int*   sidx = (int*)(Ks + 6 * 64 * 72);          // [1056] idx window
    float* red_m = (float*)(sidx + 1056);            // [32][8]
    float* red_s = red_m + 256;                      // [32][8]

    int s0 = blockIdx.x * 32;
    int bh = blockIdx.y;
    int b = bh / NH, h = bh % NH;
    int tid = threadIdx.x;
    int w = tid >> 5, lane = tid & 31;
    int quad = lane >> 2, qt = lane & 3;
    int wm = (w >> 3) * 16;
    int wn = (w & 7) * 8;
    int nw = w & 7;

    const __half* kptr = g_k + ((long long)b * SEQ) * HID + h * D;
    unsigned ks_base = (unsigned)__cvta_generic_to_shared(Ks);

    int r0 = tid >> 3, g0 = tid & 7;

    auto issue_k = [&](int cc) {
        int slot = cc % 6;
        cp_async16(ks_base + (unsigned)((slot * 64 + r0) * 72 + g0 * 8) * 2,
                   kptr + (long long)(cc * 64 + r0) * HID + g0 * 8);
        asm volatile("cp.async.commit_group;\n");
    };

    issue_k(0); issue_k(1); issue_k(2); issue_k(3);

    // q tile + index window loads (all before the single sync)
    {
        int m = tid >> 4, c = (tid & 15) * 4;
        *reinterpret_cast<uint2*>(Qs + m * 72 + c) =
            *reinterpret_cast<const uint2*>(
                g_q + ((long long)(b * SEQ + s0 + m)) * HID + h * D + c);
    }
    for (int i = tid; i < 1056; i += 512) sidx[i] = g_c2pidx[s0 + i];
    __syncthreads();

    unsigned areg[4][4];
#pragma unroll
    for (int ks = 0; ks < 4; ks++) {
        int k0 = ks * 16;
        areg[ks][0] = *reinterpret_cast<const unsigned*>(Qs + (wm + quad) * 72 + k0 + 2 * qt);
        areg[ks][1] = *reinterpret_cast<const unsigned*>(Qs + (wm + quad + 8) * 72 + k0 + 2 * qt);
        areg[ks][2] = *reinterpret_cast<const unsigned*>(Qs + (wm + quad) * 72 + k0 + 2 * qt + 8);
        areg[ks][3] = *reinterpret_cast<const unsigned*>(Qs + (wm + quad + 8) * 72 + k0 + 2 * qt + 8);
    }

    float acc[16][4];
#pragma unroll
    for (int f = 0; f < 16; f++)
#pragma unroll
        for (int j = 0; j < 4; j++) acc[f][j] = 0.0f;

    const float inv = rsqrtf(192.0f);
    int sl0 = wm + quad;
    long long c2pb0 = ((long long)h * BS + b * SEQ + s0 + sl0) * POS;
    long long c2pb1 = c2pb0 + 8LL * POS;
    long long pTb = (long long)h * POS * BS + (long long)b * SEQ;
    float rmax[2] = {-1e30f, -1e30f};

    auto do_chunk = [&](int c) {
        int slot = c % 6;
        int colb = c * 64 + wn + qt * 2;
        // --- phase 1: gather loads (independent of MMA results) ---
        __half hc[2][2], hp[2][2];
#pragma unroll
        for (int rh = 0; rh < 2; rh++) {
            long long cb = rh ? c2pb1 : c2pb0;
            int base = sl0 + rh * 8 + 1023 - colb;   // smem idx position for e=0
            int ci0 = sidx[base];
            int ci1 = sidx[base - 1];
            hc[rh][0] = __ldg(&g_c2p[cb + ci0]);
            hc[rh][1] = __ldg(&g_c2p[cb + ci1]);
            hp[rh][0] = __ldg(&g_p2cT[pTb + (long long)ci0 * BS + colb]);
            hp[rh][1] = __ldg(&g_p2cT[pTb + (long long)ci1 * BS + colb + 1]);
        }
        // --- phase 2: MMAs (cover gather latency) ---
        const __half* kb = Ks + (slot * 64 + wn + quad) * 72;
#pragma unroll
        for (int ks = 0; ks < 4; ks++) {
            int k0 = ks * 16;
            unsigned b0 = *reinterpret_cast<const unsigned*>(kb + k0 + 2 * qt);
            unsigned b1 = *reinterpret_cast<const unsigned*>(kb + k0 + 2 * qt + 8);
            mma_fp16(acc[c], areg[ks], b0, b1);
        }
        // --- phase 3: combine ---
#pragma unroll
        for (int rh = 0; rh < 2; rh++)
#pragma unroll
            for (int e = 0; e < 2; e++) {
                float x = acc[c][rh * 2 + e]
                        + __half2float(hc[rh][e]) + __half2float(hp[rh][e]);
                x *= inv;
                acc[c][rh * 2 + e] = x;
                rmax[rh] = fmaxf(rmax[rh], x);
            }
    };

#pragma unroll
    for (int c = 0; c < 16; c += 2) {
        asm volatile("cp.async.wait_group %0;\n" :: "n"(2));
        __syncthreads();
        if (c + 4 < 16) issue_k(c + 4);
        else            asm volatile("cp.async.commit_group;\n");
        if (c + 5 < 16) issue_k(c + 5);
        else            asm volatile("cp.async.commit_group;\n");
        do_chunk(c);
        do_chunk(c + 1);
    }

#pragma unroll
    for (int o = 1; o <= 2; o <<= 1) {
        rmax[0] = fmaxf(rmax[0], __shfl_xor_sync(0xffffffffu, rmax[0], o));
        rmax[1] = fmaxf(rmax[1], __shfl_xor_sync(0xffffffffu, rmax[1], o));
    }
    if (qt == 0) { red_m[sl0 * 8 + nw] = rmax[0]; red_m[(sl0 + 8) * 8 + nw] = rmax[1]; }
    __syncthreads();
    float mrow[2];
#pragma unroll
    for (int rh = 0; rh < 2; rh++) {
        float m = red_m[(sl0 + rh * 8) * 8];
#pragma unroll
        for (int j = 1; j < 8; j++) m = fmaxf(m, red_m[(sl0 + rh * 8) * 8 + j]);
        mrow[rh] = m;
    }
    float rsum[2] = {0.0f, 0.0f};
#pragma unroll
    for (int f = 0; f < 16; f++)
#pragma unroll
        for (int rh = 0; rh < 2; rh++)
#pragma unroll
            for (int e = 0; e < 2; e++) {
                float v = __expf(acc[f][rh * 2 + e] - mrow[rh]);
                acc[f][rh * 2 + e] = v;
                rsum[rh] += v;
            }
#pragma unroll
    for (int o = 1; o <= 2; o <<= 1) {
        rsum[0] += __shfl_xor_sync(0xffffffffu, rsum[0], o);
        rsum[1] += __shfl_xor_sync(0xffffffffu, rsum[1], o);
    }
    if (qt == 0) { red_s[sl0 * 8 + nw] = rsum[0]; red_s[(sl0 + 8) * 8 + nw] = rsum[1]; }
    __syncthreads();
    float rinv[2];
#pragma unroll
    for (int rh = 0; rh < 2; rh++) {
        float sum = 0.0f;
#pragma unroll
        for (int j = 0; j < 8; j++) sum += red_s[(sl0 + rh * 8) * 8 + j];
        rinv[rh] = 1.0f / sum;
    }
#pragma unroll
    for (int rh = 0; rh < 2; rh++) {
        long long rowoff = ((long long)bh * SEQ + s0 + sl0 + rh * 8) * SEQ;
        float* prow = probs + rowoff;
        __half* prow16 = g_probs16 + rowoff;
#pragma unroll
        for (int f = 0; f < 16; f++) {
            int colb = f * 64 + wn + qt * 2;
            float p0 = acc[f][rh * 2] * rinv[rh];
            float p1 = acc[f][rh * 2 + 1] * rinv[rh];
            *reinterpret_cast<float2*>(&prow[colb]) = make_float2(p0, p1);
            *reinterpret_cast<__half2*>(&prow16[colb]) = __floats2half2_rn(p0, p1);
        }
    }
}

// ctx16 = probs16 @ v16^T  (fp16, K=1024)
__global__ void __launch_bounds__(256, 2) k_ctx() {
    int z = blockIdx.y;
    int b = z / NH, h = z % NH;
    gemm16_body<0, 128, 64>(g_probs16 + (size_t)z * SEQ * SEQ, SEQ,
                            g_v16 + (size_t)z * D * SEQ, SEQ,
                            nullptr, nullptr, 0,
                            g_ctx16 + (size_t)(b * SEQ) * HID + h * D, HID, SEQ,
                            blockIdx.x * 128, 0);
}

// out-proj: fp16 MMA, fp32 bias+resid, fp32 output
__global__ void __launch_bounds__(256, 2) k_out(const float* __restrict__ hs,
                                                const float* __restrict__ bo) {
    gemm16_body<2, 128, 128>(g_ctx16, HID, g_wo16, HID, bo, hs, HID, g_pre, HID, HID,
                             blockIdx.y * 128, blockIdx.x * 128);
}

// -------- layernorm over rows of g_pre --------
__global__ void ln_kernel(const float* __restrict__ lnw, const float* __restrict__ lnb,
                          float* __restrict__ out) {
    int row = blockIdx.x;
    const float* x = g_pre + (long long)row * HID;
    float* o = out + (long long)row * HID;
    int tid = threadIdx.x;
    __shared__ float red[8];
    float v[3];
    float s = 0.0f;
#pragma unroll
    for (int k = 0; k < 3; k++) {
        v[k] = x[tid + k * 256];
        s += v[k];
    }
#pragma unroll
    for (int o2 = 16; o2; o2 >>= 1) s += __shfl_xor_sync(0xffffffffu, s, o2);
    if ((tid & 31) == 0) red[tid >> 5] = s;
    __syncthreads();
    if (tid == 0) {
        float x2 = 0.0f;
#pragma unroll
        for (int i = 0; i < 8; i++) x2 += red[i];
        red[0] = x2;
    }
    __syncthreads();
    float mu = red[0] / (float)HID;
    __syncthreads();
    float sq = 0.0f;
#pragma unroll
    for (int k = 0; k < 3; k++) {
        float d = v[k] - mu;
        sq += d * d;
    }
#pragma unroll
    for (int o2 = 16; o2; o2 >>= 1) sq += __shfl_xor_sync(0xffffffffu, sq, o2);
    if ((tid & 31) == 0) red[tid >> 5] = sq;
    __syncthreads();
    if (tid == 0) {
        float x2 = 0.0f;
#pragma unroll
        for (int i = 0; i < 8; i++) x2 += red[i];
        red[0] = x2;
    }
    __syncthreads();
    float var = red[0] / (float)HID;
    float rstd = 1.0f / sqrtf(var + 1e-7f);
#pragma unroll
    for (int k = 0; k < 3; k++) {
        int c = tid + k * 256;
        o[c] = lnw[c] * (v[k] - mu) * rstd + lnb[c];
    }
}

extern "C" void kernel_launch(void* const* d_in, const int* in_sizes, int n_in,
                              void* d_out, int out_size) {
    const float* hs  = (const float*)d_in[0];
    const float* rel = (const float*)d_in[1];
    const float* Wq  = (const float*)d_in[2];
    const float* bq  = (const float*)d_in[3];
    const float* Wk  = (const float*)d_in[4];
    const float* bk  = (const float*)d_in[5];
    const float* Wv  = (const float*)d_in[6];
    const float* bv  = (const float*)d_in[7];
    const float* Wo  = (const float*)d_in[8];
    const float* bo  = (const float*)d_in[9];
    const float* lnw = (const float*)d_in[10];
    const float* lnb = (const float*)d_in[11];

    float* out   = (float*)d_out;
    float* probs = out + (size_t)BS * HID;

    const int G16_N128_SMEM = 4 * 256 * 40 * 2;  // 81920
    const int G16_N64_SMEM  = 4 * 192 * 40 * 2;  // 61440
    const int FUSED_SMEM = (32 * 72 + 6 * 64 * 72) * 2 + 1056 * 4 + 512 * 4;  // 66176

    cudaFuncSetAttribute(k_proj,   cudaFuncAttributeMaxDynamicSharedMemorySize, G16_N128_SMEM);
    cudaFuncSetAttribute(k_posatt, cudaFuncAttributeMaxDynamicSharedMemorySize, G16_N128_SMEM);
    cudaFuncSetAttribute(k_out,    cudaFuncAttributeMaxDynamicSharedMemorySize, G16_N128_SMEM);
    cudaFuncSetAttribute(k_ctx,    cudaFuncAttributeMaxDynamicSharedMemorySize, G16_N64_SMEM);
    cudaFuncSetAttribute(k_fused_scores, cudaFuncAttributeMaxDynamicSharedMemorySize, FUSED_SMEM);

    relb_kernel<<<8, 256>>>();
    k_prep<<<dim3((BS * HID + 255) / 256, 6), 256>>>(hs, rel, Wq, Wk, Wv, Wo);
    k_proj<<<dim3(HID / 128, 104), 256, G16_N128_SMEM>>>(bq, bk, bv);
    k_posatt<<<3072, 256, G16_N128_SMEM>>>();
    k_fused_scores<<<dim3(SEQ / 32, BAT * NH), 512, FUSED_SMEM>>>(probs);
    k_ctx<<<dim3(SEQ / 128, BAT * NH), 256, G16_N64_SMEM>>>();
    k_out<<<dim3(HID / 128, BS / 128), 256, G16_N128_SMEM>>>(hs, bo);
    ln_kernel<<<BS, 256>>>(lnw, lnb, out);
}